// round 6
// baseline (speedup 1.0000x reference)
#include <cuda_runtime.h>
#include <cuda_bf16.h>
#include <math.h>
#include <stdint.h>

#define B_      32
#define N_      1024
#define C_      512
#define K_      4096
#define NSCALES 11
#define TOT     (B_*N_*C_)      // 16777216
#define MMAX    (B_*1024)       // 32768

// ---------- static device scratch ----------
__device__ float  g_frest[TOT];
__device__ float  g_fhat[TOT];
__device__ float  g_z[MMAX * C_];
__device__ float  g_logits[(size_t)MMAX * K_];
__device__ float  g_h[MMAX * C_];
__device__ float  g_wr[K_ * C_];     // tf32-rounded W   (4096 x 512)
__device__ float  g_wt[C_ * K_];     // tf32-rounded W^T (512 x 4096)
__device__ float  g_wsq[K_];
__device__ double g_sum;

// ---------- helpers ----------
__device__ __forceinline__ float tf32r(float x) {
    float y;
    asm("cvt.rna.tf32.f32 %0, %1;" : "=f"(y) : "f"(x));
    return y;
}
__device__ __forceinline__ uint32_t smem_u32(const void* p) {
    uint32_t a;
    asm("{ .reg .u64 t; cvta.to.shared.u64 t, %1; cvt.u32.u64 %0, t; }" : "=r"(a) : "l"(p));
    return a;
}
__device__ __forceinline__ void cp_async16(uint32_t saddr, const void* gaddr) {
    asm volatile("cp.async.cg.shared.global [%0], [%1], 16;" :: "r"(saddr), "l"(gaddr));
}
__device__ __forceinline__ void cp_commit() {
    asm volatile("cp.async.commit_group;" ::: "memory");
}
__device__ __forceinline__ void ldm_x4(uint32_t* r, uint32_t addr) {
    asm volatile("ldmatrix.sync.aligned.m8n8.x4.shared.b16 {%0,%1,%2,%3}, [%4];"
                 : "=r"(r[0]), "=r"(r[1]), "=r"(r[2]), "=r"(r[3]) : "r"(addr));
}
__device__ __forceinline__ void mma_tf32(float* d, const uint32_t* a, const uint32_t* b) {
    asm volatile(
        "mma.sync.aligned.m16n8k8.row.col.f32.tf32.tf32.f32 "
        "{%0,%1,%2,%3}, {%4,%5,%6,%7}, {%8,%9}, {%0,%1,%2,%3};"
        : "+f"(d[0]), "+f"(d[1]), "+f"(d[2]), "+f"(d[3])
        : "r"(a[0]), "r"(a[1]), "r"(a[2]), "r"(a[3]), "r"(b[0]), "r"(b[1]));
}

// ---------- init ----------
__global__ void init_copy(const float* __restrict__ f) {
    int i = blockIdx.x * blockDim.x + threadIdx.x;
    ((float4*)g_frest)[i] = ((const float4*)f)[i];
    ((float4*)g_fhat)[i] = make_float4(0.f, 0.f, 0.f, 0.f);
    if (i == 0) g_sum = 0.0;
}

// ---------- prep: w_sq (raw W) + tf32-rounded W and W^T ----------
__global__ void prep_w(const float* __restrict__ W) {
    int k = blockIdx.x;
    int tid = threadIdx.x;                           // 128 threads
    float s = 0.f;
#pragma unroll
    for (int i = 0; i < 4; i++) {
        int c = tid + i * 128;
        float v = W[k * C_ + c];
        s += v * v;
        float r = tf32r(v);
        g_wr[k * C_ + c] = r;
        g_wt[(size_t)c * K_ + k] = r;
    }
    for (int o = 16; o; o >>= 1) s += __shfl_xor_sync(0xffffffffu, s, o);
    __shared__ float sr[4];
    if ((tid & 31) == 0) sr[tid >> 5] = s;
    __syncthreads();
    if (tid == 0) g_wsq[k] = sr[0] + sr[1] + sr[2] + sr[3];
}

// ---------- downsample (tf32-rounded output) ----------
__global__ void downsample_kernel(int pn) {
    int c = blockIdx.y * 128 + threadIdx.x;
    int m = blockIdx.x;
    int b = m / pn;
    int j = m - b * pn;
    int L = N_ / pn;
    const float* src = g_frest + ((size_t)b * N_ + (size_t)j * L) * C_ + c;
    float s0 = 0.f, s1 = 0.f, s2 = 0.f, s3 = 0.f;
    int n = 0;
    for (; n + 4 <= L; n += 4) {
        s0 += src[(n + 0) * C_];
        s1 += src[(n + 1) * C_];
        s2 += src[(n + 2) * C_];
        s3 += src[(n + 3) * C_];
    }
    for (; n < L; n++) s0 += src[n * C_];
    g_z[m * C_ + c] = tf32r((s0 + s1 + s2 + s3) * (1.0f / (float)L));
}

// ---------- mma.sync tf32 GEMM (NT): D[m,n] = alpha * sum_k A[m,k]*B[n,k] ----------
// Tile 128x256, BK=32, 256 threads (8 warps: 2 in M x 4 in N; warp tile 64x64).
// 3-stage cp.async pipeline; fragments via ldmatrix.b16 on XOR-swizzled smem.
#define TILE_M 128
#define TILE_N 256
#define BK     32
#define A_STG  (TILE_M * BK)                 // 4096 floats
#define B_STG  (TILE_N * BK)                 // 8192 floats
#define STG    (A_STG + B_STG)               // 12288 floats = 48 KB
#define GEMM_SMEM (3 * STG * 4)              // 147456 B

__global__ __launch_bounds__(256, 1)
void gemm_mma(const float* __restrict__ A, const float* __restrict__ B,
              float* __restrict__ D, int M, int lda, int ldb, int Ntot, int Ktot,
              float alpha)
{
    extern __shared__ float smem[];
    int tid = threadIdx.x, wid = tid >> 5, lane = tid & 31;
    int m0 = blockIdx.y * TILE_M, n0 = blockIdx.x * TILE_N;
    int wm = wid & 1, wn = wid >> 1;           // warp coords: 2(M) x 4(N)
    uint32_t sbase = smem_u32(smem);

    float acc[4][8][4];
#pragma unroll
    for (int i = 0; i < 4; i++)
#pragma unroll
        for (int j = 0; j < 8; j++)
#pragma unroll
            for (int q = 0; q < 4; q++) acc[i][j][q] = 0.f;

    int ld_r = tid >> 3;
    int ld_u = tid & 7;

    // ldmatrix per-thread invariants
    int arow_b = wm * 64 + (lane & 15);
    int ahk    = (lane >> 4) & 1;
    int brow_b = wn * 64 + (lane & 7) + ((lane & 16) ? 8 : 0);
    int bhk    = (lane >> 3) & 1;

    int NS = Ktot / BK;

    // stage loader
    auto stage_load = [&](int s, int buf) {
        uint32_t base = sbase + (uint32_t)buf * (STG << 2);
        int kt = s * BK;
#pragma unroll
        for (int i = 0; i < 4; i++) {
            int r = ld_r + i * 32;
            int rr = min(m0 + r, M - 1);
            uint32_t sa = base + ((r * 8 + (ld_u ^ (r & 7))) << 4);
            cp_async16(sa, A + (size_t)rr * lda + kt + ld_u * 4);
        }
#pragma unroll
        for (int i = 0; i < 8; i++) {
            int r = ld_r + i * 32;
            uint32_t sb2 = base + (A_STG << 2) + ((r * 8 + (ld_u ^ (r & 7))) << 4);
            cp_async16(sb2, B + (size_t)(n0 + r) * ldb + kt + ld_u * 4);
        }
        cp_commit();
    };

    stage_load(0, 0);
    if (NS > 1) stage_load(1, 1);

    int buf = 0;
    for (int s = 0; s < NS; s++) {
        if (s + 1 < NS) asm volatile("cp.async.wait_group 1;" ::: "memory");
        else            asm volatile("cp.async.wait_group 0;" ::: "memory");
        __syncthreads();
        if (s + 2 < NS) {
            int nb = buf + 2; if (nb >= 3) nb -= 3;
            stage_load(s + 2, nb);
        }
        uint32_t sA = sbase + (uint32_t)buf * (STG << 2);
        uint32_t sB = sA + (A_STG << 2);
#pragma unroll
        for (int ks = 0; ks < 4; ks++) {
            uint32_t bfr[8][2];
#pragma unroll
            for (int g = 0; g < 4; g++) {
                uint32_t r4[4];
                int row = brow_b + g * 16;
                int unit = ks * 2 + bhk;
                uint32_t addr = sB + ((row * 8 + (unit ^ (row & 7))) << 4);
                ldm_x4(r4, addr);
                bfr[2 * g + 0][0] = r4[0]; bfr[2 * g + 0][1] = r4[1];
                bfr[2 * g + 1][0] = r4[2]; bfr[2 * g + 1][1] = r4[3];
            }
#pragma unroll
            for (int mf = 0; mf < 4; mf++) {
                uint32_t afr[4];
                int row = arow_b + mf * 16;
                int unit = ks * 2 + ahk;
                uint32_t addr = sA + ((row * 8 + (unit ^ (row & 7))) << 4);
                ldm_x4(afr, addr);
#pragma unroll
                for (int nf = 0; nf < 8; nf++)
                    mma_tf32(acc[mf][nf], afr, bfr[nf]);
            }
        }
        buf++; if (buf >= 3) buf -= 3;
    }

    // ---- epilogue ----
    int er = lane >> 2;            // 0..7
    int ec = (lane & 3) * 2;
#pragma unroll
    for (int mf = 0; mf < 4; mf++) {
#pragma unroll
        for (int half = 0; half < 2; half++) {
            int row = m0 + wm * 64 + mf * 16 + er + half * 8;
            if (row < M) {
                float* Drow = D + (size_t)row * Ntot + n0 + wn * 64 + ec;
#pragma unroll
                for (int nf = 0; nf < 8; nf++) {
                    float2 v;
                    v.x = acc[mf][nf][half * 2 + 0] * alpha;
                    v.y = acc[mf][nf][half * 2 + 1] * alpha;
                    *(float2*)(Drow + nf * 8) = v;
                }
            }
        }
    }
}

// ---------- softmax over K=4096 (in place), + w_sq, output tf32-rounded ----------
__global__ void softmax_kernel(float* __restrict__ P) {
    int m = blockIdx.x;
    float* row = P + (size_t)m * K_;
    int tid = threadIdx.x;   // 256 threads, 16 elems each
    float x[16];
    float mx = -1e30f;
#pragma unroll
    for (int i = 0; i < 4; i++) {
        int off = tid * 4 + i * 1024;
        float4 v = *(const float4*)(row + off);
        float4 w = *(const float4*)(g_wsq + off);
        x[i * 4 + 0] = v.x + w.x;
        x[i * 4 + 1] = v.y + w.y;
        x[i * 4 + 2] = v.z + w.z;
        x[i * 4 + 3] = v.w + w.w;
    }
#pragma unroll
    for (int i = 0; i < 16; i++) mx = fmaxf(mx, x[i]);
    for (int o = 16; o; o >>= 1) mx = fmaxf(mx, __shfl_xor_sync(0xffffffffu, mx, o));
    __shared__ float smax[8];
    __shared__ float ssum[8];
    if ((tid & 31) == 0) smax[tid >> 5] = mx;
    __syncthreads();
    mx = fmaxf(fmaxf(fmaxf(smax[0], smax[1]), fmaxf(smax[2], smax[3])),
               fmaxf(fmaxf(smax[4], smax[5]), fmaxf(smax[6], smax[7])));
    float s = 0.f;
#pragma unroll
    for (int i = 0; i < 16; i++) { x[i] = expf(__fsub_rn(x[i], mx)); s += x[i]; }
    for (int o = 16; o; o >>= 1) s += __shfl_xor_sync(0xffffffffu, s, o);
    if ((tid & 31) == 0) ssum[tid >> 5] = s;
    __syncthreads();
    s = ssum[0] + ssum[1] + ssum[2] + ssum[3] + ssum[4] + ssum[5] + ssum[6] + ssum[7];
#pragma unroll
    for (int i = 0; i < 4; i++) {
        int off = tid * 4 + i * 1024;
        float4 v = make_float4(tf32r(__fdiv_rn(x[i * 4 + 0], s)),
                               tf32r(__fdiv_rn(x[i * 4 + 1], s)),
                               tf32r(__fdiv_rn(x[i * 4 + 2], s)),
                               tf32r(__fdiv_rn(x[i * 4 + 3], s)));
        *(float4*)(row + off) = v;
    }
}

// ---------- upsample + f_hat/f_rest update + loss accum (+ final out) ----------
__global__ void update_kernel(const float* __restrict__ f, float* __restrict__ out,
                              int pn, int last)
{
    int i4 = blockIdx.x * blockDim.x + threadIdx.x;
    int idx = i4 << 2;
    int c = idx & (C_ - 1);
    int n = (idx >> 9) & (N_ - 1);
    int b = idx >> 19;

    float scale = (float)pn / (float)N_;
    float coord = __fsub_rn(__fmul_rn((float)n + 0.5f, scale), 0.5f);
    coord = fminf(fmaxf(coord, 0.0f), (float)(pn - 1));
    int i0 = (int)floorf(coord);
    int i1 = min(i0 + 1, pn - 1);
    float w = __fsub_rn(coord, (float)i0);
    float om = __fsub_rn(1.0f, w);

    const float* h0 = g_h + (size_t)(b * pn + i0) * C_ + c;
    const float* h1 = g_h + (size_t)(b * pn + i1) * C_ + c;
    float4 ha = *(const float4*)h0;
    float4 hb = *(const float4*)h1;
    float4 fh = *(const float4*)(g_fhat + idx);
    float4 fr = *(const float4*)(g_frest + idx);
    float4 fv = *(const float4*)(f + idx);

    float up0 = __fadd_rn(__fmul_rn(ha.x, om), __fmul_rn(hb.x, w));
    float up1 = __fadd_rn(__fmul_rn(ha.y, om), __fmul_rn(hb.y, w));
    float up2 = __fadd_rn(__fmul_rn(ha.z, om), __fmul_rn(hb.z, w));
    float up3 = __fadd_rn(__fmul_rn(ha.w, om), __fmul_rn(hb.w, w));

    fh.x = __fadd_rn(fh.x, up0); fh.y = __fadd_rn(fh.y, up1);
    fh.z = __fadd_rn(fh.z, up2); fh.w = __fadd_rn(fh.w, up3);
    fr.x = __fsub_rn(fr.x, up0); fr.y = __fsub_rn(fr.y, up1);
    fr.z = __fsub_rn(fr.z, up2); fr.w = __fsub_rn(fr.w, up3);
    *(float4*)(g_fhat + idx) = fh;
    *(float4*)(g_frest + idx) = fr;

    float t0 = __fsub_rn(fh.x, fv.x);
    float t1 = __fsub_rn(fh.y, fv.y);
    float t2 = __fsub_rn(fh.z, fv.z);
    float t3 = __fsub_rn(fh.w, fv.w);

    float sq = t0 * t0 + t1 * t1 + t2 * t2 + t3 * t3;

    if (last) {
        float4 o = make_float4(__fadd_rn(t0, fv.x), __fadd_rn(t1, fv.y),
                               __fadd_rn(t2, fv.z), __fadd_rn(t3, fv.w));
        *(float4*)(out + idx) = o;
    }

    for (int o = 16; o; o >>= 1) sq += __shfl_xor_sync(0xffffffffu, sq, o);
    __shared__ float sred[8];
    int tid = threadIdx.x;
    if ((tid & 31) == 0) sred[tid >> 5] = sq;
    __syncthreads();
    if (tid == 0) {
        float t = sred[0] + sred[1] + sred[2] + sred[3] +
                  sred[4] + sred[5] + sred[6] + sred[7];
        atomicAdd(&g_sum, (double)t);
    }
}

// ---------- scalars ----------
__global__ void finalize_kernel(float* __restrict__ out) {
    double mean = g_sum / ((double)TOT * (double)NSCALES);
    out[TOT]     = (float)(0.25 * mean);   // commit
    out[TOT + 1] = (float)mean;            // qlat
}

extern "C" void kernel_launch(void* const* d_in, const int* in_sizes, int n_in,
                              void* d_out, int out_size)
{
    const float* f = (const float*)d_in[0];   // (B, N, C) fp32
    const float* W = (const float*)d_in[1];   // (K, C)    fp32
    float* out = (float*)d_out;

    float *zp = nullptr, *lp = nullptr, *hp = nullptr, *wr = nullptr, *wt = nullptr;
    cudaGetSymbolAddress((void**)&zp, g_z);
    cudaGetSymbolAddress((void**)&lp, g_logits);
    cudaGetSymbolAddress((void**)&hp, g_h);
    cudaGetSymbolAddress((void**)&wr, g_wr);
    cudaGetSymbolAddress((void**)&wt, g_wt);

    cudaFuncSetAttribute(gemm_mma, cudaFuncAttributeMaxDynamicSharedMemorySize, GEMM_SMEM);

    init_copy<<<TOT / 4 / 256, 256>>>(f);
    prep_w<<<K_, 128>>>(W);

    for (int s = 0; s < NSCALES; s++) {
        int pn = 1 << s;
        int M = B_ * pn;
        int mt = (M + TILE_M - 1) / TILE_M;
        downsample_kernel<<<dim3(M, C_ / 128), 128>>>(pn);
        // logits = -2 * z @ Wr^T : A=z (lda=512), B=Wr (ldb=512), Ntot=4096, K=512
        gemm_mma<<<dim3(K_ / TILE_N, mt), 256, GEMM_SMEM>>>(
            zp, wr, lp, M, C_, C_, K_, C_, -2.0f);
        softmax_kernel<<<M, 256>>>(lp);
        // h = p @ W : NT with B = Wt (512 x 4096), Ntot=512, K=4096
        gemm_mma<<<dim3(C_ / TILE_N, mt), 256, GEMM_SMEM>>>(
            lp, wt, hp, M, K_, K_, C_, K_, 1.0f);
        update_kernel<<<TOT / 4 / 256, 256>>>(f, out, pn, s == NSCALES - 1 ? 1 : 0);
    }
    finalize_kernel<<<1, 1>>>(out);
}

// round 7
// speedup vs baseline: 1.0933x; 1.0933x over previous
#include <cuda_runtime.h>
#include <cuda_bf16.h>
#include <math.h>
#include <stdint.h>

#define B_      32
#define N_      1024
#define C_      512
#define K_      4096
#define NSCALES 11
#define TOT     (B_*N_*C_)      // 16777216
#define MMAX    (B_*1024)       // 32768

// ---------- static device scratch ----------
__device__ float  g_frest[TOT];
__device__ float  g_fhat[TOT];
__device__ float  g_z[MMAX * C_];
__device__ float  g_logits[(size_t)MMAX * K_];
__device__ float  g_h[MMAX * C_];
__device__ float  g_wr[K_ * C_];     // tf32-rounded W   (4096 x 512)
__device__ float  g_wt[C_ * K_];     // tf32-rounded W^T (512 x 4096)
__device__ float  g_wsq[K_];
__device__ double g_sum;

// ---------- helpers ----------
__device__ __forceinline__ float tf32r(float x) {
    float y;
    asm("cvt.rna.tf32.f32 %0, %1;" : "=f"(y) : "f"(x));
    return y;
}
__device__ __forceinline__ uint32_t smem_u32(const void* p) {
    uint32_t a;
    asm("{ .reg .u64 t; cvta.to.shared.u64 t, %1; cvt.u32.u64 %0, t; }" : "=r"(a) : "l"(p));
    return a;
}
__device__ __forceinline__ void cp_async16(uint32_t saddr, const void* gaddr) {
    asm volatile("cp.async.cg.shared.global [%0], [%1], 16;" :: "r"(saddr), "l"(gaddr));
}
__device__ __forceinline__ void cp_commit() {
    asm volatile("cp.async.commit_group;" ::: "memory");
}
__device__ __forceinline__ void ldm_x4(uint32_t* r, uint32_t addr) {
    asm volatile("ldmatrix.sync.aligned.m8n8.x4.shared.b16 {%0,%1,%2,%3}, [%4];"
                 : "=r"(r[0]), "=r"(r[1]), "=r"(r[2]), "=r"(r[3]) : "r"(addr));
}
__device__ __forceinline__ void mma_tf32(float* d, const uint32_t* a, const uint32_t* b) {
    asm volatile(
        "mma.sync.aligned.m16n8k8.row.col.f32.tf32.tf32.f32 "
        "{%0,%1,%2,%3}, {%4,%5,%6,%7}, {%8,%9}, {%0,%1,%2,%3};"
        : "+f"(d[0]), "+f"(d[1]), "+f"(d[2]), "+f"(d[3])
        : "r"(a[0]), "r"(a[1]), "r"(a[2]), "r"(a[3]), "r"(b[0]), "r"(b[1]));
}
// exp(y) for |y| <= 0.25 via degree-6 Taylor (rel err < 1e-10 in range);
// guarded exact fallback (never taken for this data distribution).
__device__ __forceinline__ float exp_small(float y) {
    if (__builtin_expect(fabsf(y) > 0.25f, 0)) return expf(y);
    float t = 1.388888889e-3f;                 // 1/720
    t = __fmaf_rn(t, y, 8.333333333e-3f);      // 1/120
    t = __fmaf_rn(t, y, 4.166666667e-2f);      // 1/24
    t = __fmaf_rn(t, y, 1.666666667e-1f);      // 1/6
    t = __fmaf_rn(t, y, 0.5f);
    t = __fmaf_rn(t, y, 1.0f);
    t = __fmaf_rn(t, y, 1.0f);
    return t;
}

// ---------- init ----------
__global__ void init_copy(const float* __restrict__ f) {
    int i = blockIdx.x * blockDim.x + threadIdx.x;
    ((float4*)g_frest)[i] = ((const float4*)f)[i];
    ((float4*)g_fhat)[i] = make_float4(0.f, 0.f, 0.f, 0.f);
    if (i == 0) g_sum = 0.0;
}

// ---------- prep: w_sq (raw W) + tf32-rounded W and W^T ----------
__global__ void prep_w(const float* __restrict__ W) {
    int k = blockIdx.x;
    int tid = threadIdx.x;                           // 128 threads
    float s = 0.f;
#pragma unroll
    for (int i = 0; i < 4; i++) {
        int c = tid + i * 128;
        float v = W[k * C_ + c];
        s += v * v;
        float r = tf32r(v);
        g_wr[k * C_ + c] = r;
        g_wt[(size_t)c * K_ + k] = r;
    }
    for (int o = 16; o; o >>= 1) s += __shfl_xor_sync(0xffffffffu, s, o);
    __shared__ float sr[4];
    if ((tid & 31) == 0) sr[tid >> 5] = s;
    __syncthreads();
    if (tid == 0) g_wsq[k] = sr[0] + sr[1] + sr[2] + sr[3];
}

// ---------- downsample (tf32-rounded output) ----------
__global__ void downsample_kernel(int pn) {
    int c = blockIdx.y * 128 + threadIdx.x;
    int m = blockIdx.x;
    int b = m / pn;
    int j = m - b * pn;
    int L = N_ / pn;
    const float* src = g_frest + ((size_t)b * N_ + (size_t)j * L) * C_ + c;
    float s0 = 0.f, s1 = 0.f, s2 = 0.f, s3 = 0.f;
    int n = 0;
    for (; n + 4 <= L; n += 4) {
        s0 += src[(n + 0) * C_];
        s1 += src[(n + 1) * C_];
        s2 += src[(n + 2) * C_];
        s3 += src[(n + 3) * C_];
    }
    for (; n < L; n++) s0 += src[n * C_];
    g_z[m * C_ + c] = tf32r((s0 + s1 + s2 + s3) * (1.0f / (float)L));
}

// ---------- mma.sync tf32 GEMM (NT): D[m,n] = alpha * sum_k A[m,k]*B[n,k] ----------
// Tile 128x128, BK=32, 256 threads (8 warps: 2 in M x 4 in N; warp tile 64x32).
// 2-stage cp.async pipeline (R4-proven config).
#define TILE_M 128
#define TILE_N 128
#define BK     32
#define STAGE_FLOATS ((TILE_M + TILE_N) * BK)      // 8192 floats = 32 KB
#define GEMM_SMEM    (2 * STAGE_FLOATS * 4)        // 64 KB

__global__ __launch_bounds__(256, 1)
void gemm_mma(const float* __restrict__ A, const float* __restrict__ B,
              float* __restrict__ D, int M, int lda, int ldb, int Ntot, int Ktot,
              float alpha)
{
    extern __shared__ float smem[];
    int tid = threadIdx.x, wid = tid >> 5, lane = tid & 31;
    int m0 = blockIdx.y * TILE_M, n0 = blockIdx.x * TILE_N;
    int wm = wid & 1, wn = wid >> 1;           // warp coords
    uint32_t sbase = smem_u32(smem);

    float acc[4][4][4];
#pragma unroll
    for (int i = 0; i < 4; i++)
#pragma unroll
        for (int j = 0; j < 4; j++)
#pragma unroll
            for (int q = 0; q < 4; q++) acc[i][j][q] = 0.f;

    int ld_r = tid >> 3;
    int ld_u = tid & 7;

    // ldmatrix per-thread invariants
    int arow = wm * 64 + (lane & 15);
    int ahk  = (lane >> 4) & 1;
    int brow = wn * 32 + (lane & 7) + ((lane & 16) ? 8 : 0);
    int sw   = lane & 7;

    int NS = Ktot / BK;

    // ---- prologue: stage 0 ----
    {
#pragma unroll
        for (int i = 0; i < 4; i++) {
            int r = ld_r + i * 32;
            int rr = min(m0 + r, M - 1);
            uint32_t sa = sbase + ((r * 8 + (ld_u ^ (r & 7))) << 4);
            cp_async16(sa, A + (size_t)rr * lda + ld_u * 4);
            uint32_t sb2 = sbase + ((TILE_M * BK) << 2) + ((r * 8 + (ld_u ^ (r & 7))) << 4);
            cp_async16(sb2, B + (size_t)(n0 + r) * ldb + ld_u * 4);
        }
        cp_commit();
    }

    for (int s = 0; s < NS; s++) {
        int cur = s & 1;
        uint32_t curbase = sbase + cur * (STAGE_FLOATS << 2);
        if (s + 1 < NS) {
            int nxt = (s + 1) & 1;
            uint32_t nbase = sbase + nxt * (STAGE_FLOATS << 2);
            int kt = (s + 1) * BK;
#pragma unroll
            for (int i = 0; i < 4; i++) {
                int r = ld_r + i * 32;
                int rr = min(m0 + r, M - 1);
                uint32_t sa = nbase + ((r * 8 + (ld_u ^ (r & 7))) << 4);
                cp_async16(sa, A + (size_t)rr * lda + kt + ld_u * 4);
                uint32_t sb2 = nbase + ((TILE_M * BK) << 2) + ((r * 8 + (ld_u ^ (r & 7))) << 4);
                cp_async16(sb2, B + (size_t)(n0 + r) * ldb + kt + ld_u * 4);
            }
            cp_commit();
            asm volatile("cp.async.wait_group 1;" ::: "memory");
        } else {
            asm volatile("cp.async.wait_group 0;" ::: "memory");
        }
        __syncthreads();

        uint32_t sA = curbase;
        uint32_t sB = curbase + ((TILE_M * BK) << 2);
#pragma unroll
        for (int ks = 0; ks < 4; ks++) {
            uint32_t bfr[4][2];
#pragma unroll
            for (int g = 0; g < 2; g++) {
                uint32_t r4[4];
                int row = brow + g * 16;
                int bhk = (lane >> 3) & 1;
                uint32_t addr = sB + ((row * 8 + ((ks * 2 + bhk) ^ sw)) << 4);
                ldm_x4(r4, addr);
                bfr[2 * g + 0][0] = r4[0]; bfr[2 * g + 0][1] = r4[1];
                bfr[2 * g + 1][0] = r4[2]; bfr[2 * g + 1][1] = r4[3];
            }
#pragma unroll
            for (int mf = 0; mf < 4; mf++) {
                uint32_t afr[4];
                int row = arow + mf * 16;
                uint32_t addr = sA + ((row * 8 + ((ks * 2 + ahk) ^ sw)) << 4);
                ldm_x4(afr, addr);
#pragma unroll
                for (int nf = 0; nf < 4; nf++)
                    mma_tf32(acc[mf][nf], afr, bfr[nf]);
            }
        }
        __syncthreads();
    }

    // ---- epilogue ----
    int er = lane >> 2;
    int ec = (lane & 3) * 2;
#pragma unroll
    for (int mf = 0; mf < 4; mf++) {
#pragma unroll
        for (int half = 0; half < 2; half++) {
            int row = m0 + wm * 64 + mf * 16 + er + half * 8;
            if (row < M) {
                float* Drow = D + (size_t)row * Ntot + n0 + wn * 32 + ec;
#pragma unroll
                for (int nf = 0; nf < 4; nf++) {
                    float2 v;
                    v.x = acc[mf][nf][half * 2 + 0] * alpha;
                    v.y = acc[mf][nf][half * 2 + 1] * alpha;
                    *(float2*)(Drow + nf * 8) = v;
                }
            }
        }
    }
}

// ---------- softmax over K=4096 (in place), + w_sq ----------
// No max pass (d range is ~[-0.05, 0.05]); poly exp (no MUFU); one rcp per row.
__global__ void softmax_kernel(float* __restrict__ P) {
    int m = blockIdx.x;
    float* row = P + (size_t)m * K_;
    int tid = threadIdx.x;   // 256 threads, 16 elems each
    float x[16];
    float s = 0.f;
#pragma unroll
    for (int i = 0; i < 4; i++) {
        int off = tid * 4 + i * 1024;
        float4 v = *(const float4*)(row + off);
        float4 w = *(const float4*)(g_wsq + off);
        x[i * 4 + 0] = exp_small(v.x + w.x);
        x[i * 4 + 1] = exp_small(v.y + w.y);
        x[i * 4 + 2] = exp_small(v.z + w.z);
        x[i * 4 + 3] = exp_small(v.w + w.w);
        s += x[i * 4 + 0] + x[i * 4 + 1] + x[i * 4 + 2] + x[i * 4 + 3];
    }
    for (int o = 16; o; o >>= 1) s += __shfl_xor_sync(0xffffffffu, s, o);
    __shared__ float ssum[8];
    if ((tid & 31) == 0) ssum[tid >> 5] = s;
    __syncthreads();
    s = ssum[0] + ssum[1] + ssum[2] + ssum[3] + ssum[4] + ssum[5] + ssum[6] + ssum[7];
    float rinv = __frcp_rn(s);
#pragma unroll
    for (int i = 0; i < 4; i++) {
        int off = tid * 4 + i * 1024;
        float4 v = make_float4(tf32r(__fmul_rn(x[i * 4 + 0], rinv)),
                               tf32r(__fmul_rn(x[i * 4 + 1], rinv)),
                               tf32r(__fmul_rn(x[i * 4 + 2], rinv)),
                               tf32r(__fmul_rn(x[i * 4 + 3], rinv)));
        *(float4*)(row + off) = v;
    }
}

// ---------- upsample + f_hat/f_rest update + loss accum (+ final out) ----------
__global__ void update_kernel(const float* __restrict__ f, float* __restrict__ out,
                              int pn, int last)
{
    int i4 = blockIdx.x * blockDim.x + threadIdx.x;
    int idx = i4 << 2;
    int c = idx & (C_ - 1);
    int n = (idx >> 9) & (N_ - 1);
    int b = idx >> 19;

    float scale = (float)pn / (float)N_;
    float coord = __fsub_rn(__fmul_rn((float)n + 0.5f, scale), 0.5f);
    coord = fminf(fmaxf(coord, 0.0f), (float)(pn - 1));
    int i0 = (int)floorf(coord);
    int i1 = min(i0 + 1, pn - 1);
    float w = __fsub_rn(coord, (float)i0);
    float om = __fsub_rn(1.0f, w);

    const float* h0 = g_h + (size_t)(b * pn + i0) * C_ + c;
    const float* h1 = g_h + (size_t)(b * pn + i1) * C_ + c;
    float4 ha = *(const float4*)h0;
    float4 hb = *(const float4*)h1;
    float4 fh = *(const float4*)(g_fhat + idx);
    float4 fr = *(const float4*)(g_frest + idx);
    float4 fv = *(const float4*)(f + idx);

    float up0 = __fadd_rn(__fmul_rn(ha.x, om), __fmul_rn(hb.x, w));
    float up1 = __fadd_rn(__fmul_rn(ha.y, om), __fmul_rn(hb.y, w));
    float up2 = __fadd_rn(__fmul_rn(ha.z, om), __fmul_rn(hb.z, w));
    float up3 = __fadd_rn(__fmul_rn(ha.w, om), __fmul_rn(hb.w, w));

    fh.x = __fadd_rn(fh.x, up0); fh.y = __fadd_rn(fh.y, up1);
    fh.z = __fadd_rn(fh.z, up2); fh.w = __fadd_rn(fh.w, up3);
    fr.x = __fsub_rn(fr.x, up0); fr.y = __fsub_rn(fr.y, up1);
    fr.z = __fsub_rn(fr.z, up2); fr.w = __fsub_rn(fr.w, up3);
    *(float4*)(g_fhat + idx) = fh;
    *(float4*)(g_frest + idx) = fr;

    float t0 = __fsub_rn(fh.x, fv.x);
    float t1 = __fsub_rn(fh.y, fv.y);
    float t2 = __fsub_rn(fh.z, fv.z);
    float t3 = __fsub_rn(fh.w, fv.w);

    float sq = t0 * t0 + t1 * t1 + t2 * t2 + t3 * t3;

    if (last) {
        float4 o = make_float4(__fadd_rn(t0, fv.x), __fadd_rn(t1, fv.y),
                               __fadd_rn(t2, fv.z), __fadd_rn(t3, fv.w));
        *(float4*)(out + idx) = o;
    }

    for (int o = 16; o; o >>= 1) sq += __shfl_xor_sync(0xffffffffu, sq, o);
    __shared__ float sred[8];
    int tid = threadIdx.x;
    if ((tid & 31) == 0) sred[tid >> 5] = sq;
    __syncthreads();
    if (tid == 0) {
        float t = sred[0] + sred[1] + sred[2] + sred[3] +
                  sred[4] + sred[5] + sred[6] + sred[7];
        atomicAdd(&g_sum, (double)t);
    }
}

// ---------- scalars ----------
__global__ void finalize_kernel(float* __restrict__ out) {
    double mean = g_sum / ((double)TOT * (double)NSCALES);
    out[TOT]     = (float)(0.25 * mean);   // commit
    out[TOT + 1] = (float)mean;            // qlat
}

extern "C" void kernel_launch(void* const* d_in, const int* in_sizes, int n_in,
                              void* d_out, int out_size)
{
    const float* f = (const float*)d_in[0];   // (B, N, C) fp32
    const float* W = (const float*)d_in[1];   // (K, C)    fp32
    float* out = (float*)d_out;

    float *zp = nullptr, *lp = nullptr, *hp = nullptr, *wr = nullptr, *wt = nullptr;
    cudaGetSymbolAddress((void**)&zp, g_z);
    cudaGetSymbolAddress((void**)&lp, g_logits);
    cudaGetSymbolAddress((void**)&hp, g_h);
    cudaGetSymbolAddress((void**)&wr, g_wr);
    cudaGetSymbolAddress((void**)&wt, g_wt);

    cudaFuncSetAttribute(gemm_mma, cudaFuncAttributeMaxDynamicSharedMemorySize, GEMM_SMEM);

    init_copy<<<TOT / 4 / 256, 256>>>(f);
    prep_w<<<K_, 128>>>(W);

    for (int s = 0; s < NSCALES; s++) {
        int pn = 1 << s;
        int M = B_ * pn;
        int mt = (M + TILE_M - 1) / TILE_M;
        downsample_kernel<<<dim3(M, C_ / 128), 128>>>(pn);
        // logits = -2 * z @ Wr^T : A=z (lda=512), B=Wr (ldb=512), Ntot=4096, K=512
        gemm_mma<<<dim3(K_ / TILE_N, mt), 256, GEMM_SMEM>>>(
            zp, wr, lp, M, C_, C_, K_, C_, -2.0f);
        softmax_kernel<<<M, 256>>>(lp);
        // h = p @ W : NT with B = Wt (512 x 4096), Ntot=512, K=4096
        gemm_mma<<<dim3(C_ / TILE_N, mt), 256, GEMM_SMEM>>>(
            lp, wt, hp, M, K_, K_, C_, K_, 1.0f);
        update_kernel<<<TOT / 4 / 256, 256>>>(f, out, pn, s == NSCALES - 1 ? 1 : 0);
    }
    finalize_kernel<<<1, 1>>>(out);
}

// round 8
// speedup vs baseline: 1.1593x; 1.0603x over previous
#include <cuda_runtime.h>
#include <cuda_bf16.h>
#include <math.h>
#include <stdint.h>

#define B_      32
#define N_      1024
#define C_      512
#define K_      4096
#define NSCALES 11
#define TOT     (B_*N_*C_)      // 16777216
#define MMAX    (B_*1024)       // 32768

// ---------- static device scratch ----------
__device__ float  g_frest[TOT];
__device__ float  g_fhat[TOT];
__device__ float  g_z[MMAX * C_];
__device__ float  g_e[(size_t)MMAX * K_];    // exp(d) (pre-normalization)
__device__ float  g_h[MMAX * C_];
__device__ float  g_wr[K_ * C_];             // tf32-rounded W   (4096 x 512)
__device__ float  g_wt[C_ * K_];             // tf32-rounded W^T (512 x 4096)
__device__ float  g_wsq[K_];
__device__ float  g_S[MMAX];                 // softmax row sums
__device__ double g_sum;

// ---------- helpers ----------
__device__ __forceinline__ float tf32r(float x) {
    float y;
    asm("cvt.rna.tf32.f32 %0, %1;" : "=f"(y) : "f"(x));
    return y;
}
__device__ __forceinline__ uint32_t smem_u32(const void* p) {
    uint32_t a;
    asm("{ .reg .u64 t; cvta.to.shared.u64 t, %1; cvt.u32.u64 %0, t; }" : "=r"(a) : "l"(p));
    return a;
}
__device__ __forceinline__ void cp_async16(uint32_t saddr, const void* gaddr) {
    asm volatile("cp.async.cg.shared.global [%0], [%1], 16;" :: "r"(saddr), "l"(gaddr));
}
__device__ __forceinline__ void cp_commit() {
    asm volatile("cp.async.commit_group;" ::: "memory");
}
__device__ __forceinline__ void ldm_x4(uint32_t* r, uint32_t addr) {
    asm volatile("ldmatrix.sync.aligned.m8n8.x4.shared.b16 {%0,%1,%2,%3}, [%4];"
                 : "=r"(r[0]), "=r"(r[1]), "=r"(r[2]), "=r"(r[3]) : "r"(addr));
}
__device__ __forceinline__ void mma_tf32(float* d, const uint32_t* a, const uint32_t* b) {
    asm volatile(
        "mma.sync.aligned.m16n8k8.row.col.f32.tf32.tf32.f32 "
        "{%0,%1,%2,%3}, {%4,%5,%6,%7}, {%8,%9}, {%0,%1,%2,%3};"
        : "+f"(d[0]), "+f"(d[1]), "+f"(d[2]), "+f"(d[3])
        : "r"(a[0]), "r"(a[1]), "r"(a[2]), "r"(a[3]), "r"(b[0]), "r"(b[1]));
}
// exp(y) for |y| <= 0.25 via degree-6 Taylor; guarded exact fallback.
__device__ __forceinline__ float exp_small(float y) {
    if (__builtin_expect(fabsf(y) > 0.25f, 0)) return expf(y);
    float t = 1.388888889e-3f;
    t = __fmaf_rn(t, y, 8.333333333e-3f);
    t = __fmaf_rn(t, y, 4.166666667e-2f);
    t = __fmaf_rn(t, y, 1.666666667e-1f);
    t = __fmaf_rn(t, y, 0.5f);
    t = __fmaf_rn(t, y, 1.0f);
    t = __fmaf_rn(t, y, 1.0f);
    return t;
}

// ---------- init ----------
__global__ void init_copy(const float* __restrict__ f) {
    int i = blockIdx.x * blockDim.x + threadIdx.x;
    ((float4*)g_frest)[i] = ((const float4*)f)[i];
    ((float4*)g_fhat)[i] = make_float4(0.f, 0.f, 0.f, 0.f);
    if (i == 0) g_sum = 0.0;
}

// ---------- prep: w_sq (raw W) + tf32-rounded W and W^T ----------
__global__ void prep_w(const float* __restrict__ W) {
    int k = blockIdx.x;
    int tid = threadIdx.x;                           // 128 threads
    float s = 0.f;
#pragma unroll
    for (int i = 0; i < 4; i++) {
        int c = tid + i * 128;
        float v = W[k * C_ + c];
        s += v * v;
        float r = tf32r(v);
        g_wr[k * C_ + c] = r;
        g_wt[(size_t)c * K_ + k] = r;
    }
    for (int o = 16; o; o >>= 1) s += __shfl_xor_sync(0xffffffffu, s, o);
    __shared__ float sr[4];
    if ((tid & 31) == 0) sr[tid >> 5] = s;
    __syncthreads();
    if (tid == 0) g_wsq[k] = sr[0] + sr[1] + sr[2] + sr[3];
}

// ---------- downsample (tf32-rounded output) + zero row sums ----------
__global__ void downsample_kernel(int pn) {
    int c = blockIdx.y * 128 + threadIdx.x;
    int m = blockIdx.x;
    if (blockIdx.y == 0 && threadIdx.x == 0) g_S[m] = 0.f;
    int b = m / pn;
    int j = m - b * pn;
    int L = N_ / pn;
    const float* src = g_frest + ((size_t)b * N_ + (size_t)j * L) * C_ + c;
    float s0 = 0.f, s1 = 0.f, s2 = 0.f, s3 = 0.f;
    int n = 0;
    for (; n + 4 <= L; n += 4) {
        s0 += src[(n + 0) * C_];
        s1 += src[(n + 1) * C_];
        s2 += src[(n + 2) * C_];
        s3 += src[(n + 3) * C_];
    }
    for (; n < L; n++) s0 += src[n * C_];
    g_z[m * C_ + c] = tf32r((s0 + s1 + s2 + s3) * (1.0f / (float)L));
}

// ---------- GEMM config ----------
#define TILE_M 128
#define TILE_N 128
#define BK     32
#define STAGE_FLOATS ((TILE_M + TILE_N) * BK)      // 8192 floats = 32 KB
#define GEMM_SMEM    (2 * STAGE_FLOATS * 4)        // 64 KB

// ---------- GEMM1 + exp fusion: E[m,n] = exp(wsq[n] - 2*sum_k z[m,k]*Wr[n,k]),
//            rowsum atomically accumulated into g_S ----------
__global__ __launch_bounds__(256, 2)
void gemm_exp(const float* __restrict__ A, const float* __restrict__ B,
              float* __restrict__ E, int M)
{
    extern __shared__ float smem[];
    const int lda = C_, ldb = C_, Ntot = K_, Ktot = C_;
    int tid = threadIdx.x, wid = tid >> 5, lane = tid & 31;
    int m0 = blockIdx.y * TILE_M, n0 = blockIdx.x * TILE_N;
    int wm = wid & 1, wn = wid >> 1;
    uint32_t sbase = smem_u32(smem);

    float acc[4][4][4];
#pragma unroll
    for (int i = 0; i < 4; i++)
#pragma unroll
        for (int j = 0; j < 4; j++)
#pragma unroll
            for (int q = 0; q < 4; q++) acc[i][j][q] = 0.f;

    int ld_r = tid >> 3;
    int ld_u = tid & 7;
    int arow = wm * 64 + (lane & 15);
    int ahk  = (lane >> 4) & 1;
    int brow = wn * 32 + (lane & 7) + ((lane & 16) ? 8 : 0);
    int sw   = lane & 7;
    int NS = Ktot / BK;

    {
#pragma unroll
        for (int i = 0; i < 4; i++) {
            int r = ld_r + i * 32;
            int rr = min(m0 + r, M - 1);
            uint32_t sa = sbase + ((r * 8 + (ld_u ^ (r & 7))) << 4);
            cp_async16(sa, A + (size_t)rr * lda + ld_u * 4);
            uint32_t sb2 = sbase + ((TILE_M * BK) << 2) + ((r * 8 + (ld_u ^ (r & 7))) << 4);
            cp_async16(sb2, B + (size_t)(n0 + r) * ldb + ld_u * 4);
        }
        cp_commit();
    }

    for (int s = 0; s < NS; s++) {
        int cur = s & 1;
        uint32_t curbase = sbase + cur * (STAGE_FLOATS << 2);
        if (s + 1 < NS) {
            uint32_t nbase = sbase + ((s + 1) & 1) * (STAGE_FLOATS << 2);
            int kt = (s + 1) * BK;
#pragma unroll
            for (int i = 0; i < 4; i++) {
                int r = ld_r + i * 32;
                int rr = min(m0 + r, M - 1);
                uint32_t sa = nbase + ((r * 8 + (ld_u ^ (r & 7))) << 4);
                cp_async16(sa, A + (size_t)rr * lda + kt + ld_u * 4);
                uint32_t sb2 = nbase + ((TILE_M * BK) << 2) + ((r * 8 + (ld_u ^ (r & 7))) << 4);
                cp_async16(sb2, B + (size_t)(n0 + r) * ldb + kt + ld_u * 4);
            }
            cp_commit();
            asm volatile("cp.async.wait_group 1;" ::: "memory");
        } else {
            asm volatile("cp.async.wait_group 0;" ::: "memory");
        }
        __syncthreads();

        uint32_t sA = curbase;
        uint32_t sB = curbase + ((TILE_M * BK) << 2);
#pragma unroll
        for (int ks = 0; ks < 4; ks++) {
            uint32_t bfr[4][2];
#pragma unroll
            for (int g = 0; g < 2; g++) {
                uint32_t r4[4];
                int row = brow + g * 16;
                int bhk = (lane >> 3) & 1;
                uint32_t addr = sB + ((row * 8 + ((ks * 2 + bhk) ^ sw)) << 4);
                ldm_x4(r4, addr);
                bfr[2 * g + 0][0] = r4[0]; bfr[2 * g + 0][1] = r4[1];
                bfr[2 * g + 1][0] = r4[2]; bfr[2 * g + 1][1] = r4[3];
            }
#pragma unroll
            for (int mf = 0; mf < 4; mf++) {
                uint32_t afr[4];
                int row = arow + mf * 16;
                uint32_t addr = sA + ((row * 8 + ((ks * 2 + ahk) ^ sw)) << 4);
                ldm_x4(afr, addr);
#pragma unroll
                for (int nf = 0; nf < 4; nf++)
                    mma_tf32(acc[mf][nf], afr, bfr[nf]);
            }
        }
        __syncthreads();
    }

    // ---- epilogue: e = exp(wsq + (-2)*acc); rowsum -> atomic g_S ----
    int er = lane >> 2;
    int ec = (lane & 3) * 2;
#pragma unroll
    for (int mf = 0; mf < 4; mf++) {
#pragma unroll
        for (int half = 0; half < 2; half++) {
            int row = m0 + wm * 64 + mf * 16 + er + half * 8;
            float rs = 0.f;
            if (row < M) {
                float* Erow = E + (size_t)row * Ntot + n0 + wn * 32 + ec;
#pragma unroll
                for (int nf = 0; nf < 4; nf++) {
                    int ncol = n0 + wn * 32 + ec + nf * 8;
                    float e0 = exp_small(__fadd_rn(__fmul_rn(acc[mf][nf][half * 2 + 0], -2.0f),
                                                   g_wsq[ncol]));
                    float e1 = exp_small(__fadd_rn(__fmul_rn(acc[mf][nf][half * 2 + 1], -2.0f),
                                                   g_wsq[ncol + 1]));
                    float2 v; v.x = e0; v.y = e1;
                    *(float2*)(Erow + nf * 8) = v;
                    rs += e0 + e1;
                }
            }
            rs += __shfl_xor_sync(0xffffffffu, rs, 1);
            rs += __shfl_xor_sync(0xffffffffu, rs, 2);
            if ((lane & 3) == 0 && row < M) atomicAdd(&g_S[row], rs);
        }
    }
}

// ---------- GEMM2 + normalize fusion: H[m,c] = sum_k tf32r(E[m,k]/S[m]) * Wt[c,k] ----------
__global__ __launch_bounds__(256, 2)
void gemm_p(const float* __restrict__ Eg, const float* __restrict__ B,
            float* __restrict__ D, int M)
{
    extern __shared__ float smem[];
    const int lda = K_, ldb = K_, Ntot = C_, Ktot = K_;
    int tid = threadIdx.x, wid = tid >> 5, lane = tid & 31;
    int m0 = blockIdx.y * TILE_M, n0 = blockIdx.x * TILE_N;
    int wm = wid & 1, wn = wid >> 1;
    uint32_t sbase = smem_u32(smem);

    float acc[4][4][4];
#pragma unroll
    for (int i = 0; i < 4; i++)
#pragma unroll
        for (int j = 0; j < 4; j++)
#pragma unroll
            for (int q = 0; q < 4; q++) acc[i][j][q] = 0.f;

    int ld_r = tid >> 3;
    int ld_u = tid & 7;
    int arow = wm * 64 + (lane & 15);
    int ahk  = (lane >> 4) & 1;
    int brow = wn * 32 + (lane & 7) + ((lane & 16) ? 8 : 0);
    int sw   = lane & 7;
    int NS = Ktot / BK;

    // per-thread A rows (fixed across stages) + rinv
    int arow_g[4];
    float rinv[4];
#pragma unroll
    for (int i = 0; i < 4; i++) {
        arow_g[i] = min(m0 + ld_r + i * 32, M - 1);
        rinv[i] = __frcp_rn(g_S[arow_g[i]]);
    }

    float4 areg[4];
    // LDG A for k-offset kt
    auto ldgA = [&](int kt) {
#pragma unroll
        for (int i = 0; i < 4; i++)
            areg[i] = *(const float4*)(Eg + (size_t)arow_g[i] * lda + kt + ld_u * 4);
    };
    // transform + STS into buffer
    auto stsA = [&](int bufsel) {
        char* base = (char*)smem + (size_t)bufsel * (STAGE_FLOATS << 2);
#pragma unroll
        for (int i = 0; i < 4; i++) {
            int r = ld_r + i * 32;
            float4 p;
            p.x = tf32r(__fmul_rn(areg[i].x, rinv[i]));
            p.y = tf32r(__fmul_rn(areg[i].y, rinv[i]));
            p.z = tf32r(__fmul_rn(areg[i].z, rinv[i]));
            p.w = tf32r(__fmul_rn(areg[i].w, rinv[i]));
            *(float4*)(base + ((r * 8 + (ld_u ^ (r & 7))) << 4)) = p;
        }
    };
    auto cpB = [&](int kt, int bufsel) {
        uint32_t base = sbase + (uint32_t)bufsel * (STAGE_FLOATS << 2) + ((TILE_M * BK) << 2);
#pragma unroll
        for (int i = 0; i < 4; i++) {
            int r = ld_r + i * 32;
            uint32_t sb2 = base + ((r * 8 + (ld_u ^ (r & 7))) << 4);
            cp_async16(sb2, B + (size_t)(n0 + r) * ldb + kt + ld_u * 4);
        }
        cp_commit();
    };

    // prologue
    ldgA(0);
    cpB(0, 0);
    stsA(0);

    for (int s = 0; s < NS; s++) {
        int cur = s & 1;
        int nxt = 1 - cur;
        if (s + 1 < NS) {
            ldgA((s + 1) * BK);
            cpB((s + 1) * BK, nxt);
            asm volatile("cp.async.wait_group 1;" ::: "memory");
        } else {
            asm volatile("cp.async.wait_group 0;" ::: "memory");
        }
        __syncthreads();

        uint32_t sA = sbase + (uint32_t)cur * (STAGE_FLOATS << 2);
        uint32_t sB = sA + ((TILE_M * BK) << 2);
#pragma unroll
        for (int ks = 0; ks < 4; ks++) {
            uint32_t bfr[4][2];
#pragma unroll
            for (int g = 0; g < 2; g++) {
                uint32_t r4[4];
                int row = brow + g * 16;
                int bhk = (lane >> 3) & 1;
                uint32_t addr = sB + ((row * 8 + ((ks * 2 + bhk) ^ sw)) << 4);
                ldm_x4(r4, addr);
                bfr[2 * g + 0][0] = r4[0]; bfr[2 * g + 0][1] = r4[1];
                bfr[2 * g + 1][0] = r4[2]; bfr[2 * g + 1][1] = r4[3];
            }
#pragma unroll
            for (int mf = 0; mf < 4; mf++) {
                uint32_t afr[4];
                int row = arow + mf * 16;
                uint32_t addr = sA + ((row * 8 + ((ks * 2 + ahk) ^ sw)) << 4);
                ldm_x4(afr, addr);
#pragma unroll
                for (int nf = 0; nf < 4; nf++)
                    mma_tf32(acc[mf][nf], afr, bfr[nf]);
            }
        }
        if (s + 1 < NS) stsA(nxt);
        __syncthreads();
    }

    // ---- epilogue ----
    int er = lane >> 2;
    int ec = (lane & 3) * 2;
#pragma unroll
    for (int mf = 0; mf < 4; mf++) {
#pragma unroll
        for (int half = 0; half < 2; half++) {
            int row = m0 + wm * 64 + mf * 16 + er + half * 8;
            if (row < M) {
                float* Drow = D + (size_t)row * Ntot + n0 + wn * 32 + ec;
#pragma unroll
                for (int nf = 0; nf < 4; nf++) {
                    float2 v;
                    v.x = acc[mf][nf][half * 2 + 0];
                    v.y = acc[mf][nf][half * 2 + 1];
                    *(float2*)(Drow + nf * 8) = v;
                }
            }
        }
    }
}

// ---------- upsample + f_hat/f_rest update + loss accum (+ final out) ----------
__global__ void update_kernel(const float* __restrict__ f, float* __restrict__ out,
                              int pn, int last)
{
    int i4 = blockIdx.x * blockDim.x + threadIdx.x;
    int idx = i4 << 2;
    int c = idx & (C_ - 1);
    int n = (idx >> 9) & (N_ - 1);
    int b = idx >> 19;

    float scale = (float)pn / (float)N_;
    float coord = __fsub_rn(__fmul_rn((float)n + 0.5f, scale), 0.5f);
    coord = fminf(fmaxf(coord, 0.0f), (float)(pn - 1));
    int i0 = (int)floorf(coord);
    int i1 = min(i0 + 1, pn - 1);
    float w = __fsub_rn(coord, (float)i0);
    float om = __fsub_rn(1.0f, w);

    const float* h0 = g_h + (size_t)(b * pn + i0) * C_ + c;
    const float* h1 = g_h + (size_t)(b * pn + i1) * C_ + c;
    float4 ha = *(const float4*)h0;
    float4 hb = *(const float4*)h1;
    float4 fh = *(const float4*)(g_fhat + idx);
    float4 fr = *(const float4*)(g_frest + idx);
    float4 fv = *(const float4*)(f + idx);

    float up0 = __fadd_rn(__fmul_rn(ha.x, om), __fmul_rn(hb.x, w));
    float up1 = __fadd_rn(__fmul_rn(ha.y, om), __fmul_rn(hb.y, w));
    float up2 = __fadd_rn(__fmul_rn(ha.z, om), __fmul_rn(hb.z, w));
    float up3 = __fadd_rn(__fmul_rn(ha.w, om), __fmul_rn(hb.w, w));

    fh.x = __fadd_rn(fh.x, up0); fh.y = __fadd_rn(fh.y, up1);
    fh.z = __fadd_rn(fh.z, up2); fh.w = __fadd_rn(fh.w, up3);
    fr.x = __fsub_rn(fr.x, up0); fr.y = __fsub_rn(fr.y, up1);
    fr.z = __fsub_rn(fr.z, up2); fr.w = __fsub_rn(fr.w, up3);
    *(float4*)(g_fhat + idx) = fh;
    *(float4*)(g_frest + idx) = fr;

    float t0 = __fsub_rn(fh.x, fv.x);
    float t1 = __fsub_rn(fh.y, fv.y);
    float t2 = __fsub_rn(fh.z, fv.z);
    float t3 = __fsub_rn(fh.w, fv.w);

    float sq = t0 * t0 + t1 * t1 + t2 * t2 + t3 * t3;

    if (last) {
        float4 o = make_float4(__fadd_rn(t0, fv.x), __fadd_rn(t1, fv.y),
                               __fadd_rn(t2, fv.z), __fadd_rn(t3, fv.w));
        *(float4*)(out + idx) = o;
    }

    for (int o = 16; o; o >>= 1) sq += __shfl_xor_sync(0xffffffffu, sq, o);
    __shared__ float sred[8];
    int tid = threadIdx.x;
    if ((tid & 31) == 0) sred[tid >> 5] = sq;
    __syncthreads();
    if (tid == 0) {
        float t = sred[0] + sred[1] + sred[2] + sred[3] +
                  sred[4] + sred[5] + sred[6] + sred[7];
        atomicAdd(&g_sum, (double)t);
    }
}

// ---------- scalars ----------
__global__ void finalize_kernel(float* __restrict__ out) {
    double mean = g_sum / ((double)TOT * (double)NSCALES);
    out[TOT]     = (float)(0.25 * mean);   // commit
    out[TOT + 1] = (float)mean;            // qlat
}

extern "C" void kernel_launch(void* const* d_in, const int* in_sizes, int n_in,
                              void* d_out, int out_size)
{
    const float* f = (const float*)d_in[0];   // (B, N, C) fp32
    const float* W = (const float*)d_in[1];   // (K, C)    fp32
    float* out = (float*)d_out;

    float *zp = nullptr, *ep = nullptr, *hp = nullptr, *wr = nullptr, *wt = nullptr;
    cudaGetSymbolAddress((void**)&zp, g_z);
    cudaGetSymbolAddress((void**)&ep, g_e);
    cudaGetSymbolAddress((void**)&hp, g_h);
    cudaGetSymbolAddress((void**)&wr, g_wr);
    cudaGetSymbolAddress((void**)&wt, g_wt);

    cudaFuncSetAttribute(gemm_exp, cudaFuncAttributeMaxDynamicSharedMemorySize, GEMM_SMEM);
    cudaFuncSetAttribute(gemm_p,   cudaFuncAttributeMaxDynamicSharedMemorySize, GEMM_SMEM);

    init_copy<<<TOT / 4 / 256, 256>>>(f);
    prep_w<<<K_, 128>>>(W);

    for (int s = 0; s < NSCALES; s++) {
        int pn = 1 << s;
        int M = B_ * pn;
        int mt = (M + TILE_M - 1) / TILE_M;
        downsample_kernel<<<dim3(M, C_ / 128), 128>>>(pn);
        // E = exp(wsq - 2 z Wr^T), rowsums in g_S
        gemm_exp<<<dim3(K_ / TILE_N, mt), 256, GEMM_SMEM>>>(zp, wr, ep, M);
        // h = tf32r(E/S) @ W  (normalize fused into A-load)
        gemm_p<<<dim3(C_ / TILE_N, mt), 256, GEMM_SMEM>>>(ep, wt, hp, M);
        update_kernel<<<TOT / 4 / 256, 256>>>(f, out, pn, s == NSCALES - 1 ? 1 : 0);
    }
    finalize_kernel<<<1, 1>>>(out);
}

// round 9
// speedup vs baseline: 1.3128x; 1.1324x over previous
#include <cuda_runtime.h>
#include <cuda_bf16.h>
#include <math.h>
#include <stdint.h>

#define B_      32
#define N_      1024
#define C_      512
#define K_      4096
#define NSCALES 11
#define TOT     (B_*N_*C_)      // 16777216
#define MMAX    (B_*1024)       // 32768

// ---------- static device scratch ----------
__device__ float  g_frest[TOT];
__device__ float  g_fhat[TOT];
__device__ float  g_z[MMAX * C_];            // RAW block sums (scaled at gemm A-load)
__device__ float  g_e[(size_t)MMAX * K_];    // exp(d) (pre-normalization)
__device__ float  g_h[MMAX * C_];
__device__ float  g_wr[K_ * C_];             // tf32-rounded W   (4096 x 512)
__device__ float  g_wt[C_ * K_];             // tf32-rounded W^T (512 x 4096)
__device__ float  g_wsq[K_];
__device__ float  g_S[MMAX];                 // softmax row sums
__device__ double g_sum;

// ---------- helpers ----------
__device__ __forceinline__ float tf32r(float x) {
    float y;
    asm("cvt.rna.tf32.f32 %0, %1;" : "=f"(y) : "f"(x));
    return y;
}
__device__ __forceinline__ uint32_t smem_u32(const void* p) {
    uint32_t a;
    asm("{ .reg .u64 t; cvta.to.shared.u64 t, %1; cvt.u32.u64 %0, t; }" : "=r"(a) : "l"(p));
    return a;
}
__device__ __forceinline__ void cp_async16(uint32_t saddr, const void* gaddr) {
    asm volatile("cp.async.cg.shared.global [%0], [%1], 16;" :: "r"(saddr), "l"(gaddr));
}
__device__ __forceinline__ void cp_commit() {
    asm volatile("cp.async.commit_group;" ::: "memory");
}
__device__ __forceinline__ void ldm_x4(uint32_t* r, uint32_t addr) {
    asm volatile("ldmatrix.sync.aligned.m8n8.x4.shared.b16 {%0,%1,%2,%3}, [%4];"
                 : "=r"(r[0]), "=r"(r[1]), "=r"(r[2]), "=r"(r[3]) : "r"(addr));
}
__device__ __forceinline__ void mma_tf32(float* d, const uint32_t* a, const uint32_t* b) {
    asm volatile(
        "mma.sync.aligned.m16n8k8.row.col.f32.tf32.tf32.f32 "
        "{%0,%1,%2,%3}, {%4,%5,%6,%7}, {%8,%9}, {%0,%1,%2,%3};"
        : "+f"(d[0]), "+f"(d[1]), "+f"(d[2]), "+f"(d[3])
        : "r"(a[0]), "r"(a[1]), "r"(a[2]), "r"(a[3]), "r"(b[0]), "r"(b[1]));
}
// exp(y) for |y| <= 0.25 via degree-6 Taylor; guarded exact fallback.
__device__ __forceinline__ float exp_small(float y) {
    if (__builtin_expect(fabsf(y) > 0.25f, 0)) return expf(y);
    float t = 1.388888889e-3f;
    t = __fmaf_rn(t, y, 8.333333333e-3f);
    t = __fmaf_rn(t, y, 4.166666667e-2f);
    t = __fmaf_rn(t, y, 1.666666667e-1f);
    t = __fmaf_rn(t, y, 0.5f);
    t = __fmaf_rn(t, y, 1.0f);
    t = __fmaf_rn(t, y, 1.0f);
    return t;
}

// ---------- init ----------
__global__ void init_copy(const float* __restrict__ f) {
    int i = blockIdx.x * blockDim.x + threadIdx.x;
    ((float4*)g_frest)[i] = ((const float4*)f)[i];
    ((float4*)g_fhat)[i] = make_float4(0.f, 0.f, 0.f, 0.f);
    if (i == 0) g_sum = 0.0;
}

// ---------- prep: w_sq (raw W) + tf32-rounded W and W^T ----------
__global__ void prep_w(const float* __restrict__ W) {
    int k = blockIdx.x;
    int tid = threadIdx.x;                           // 128 threads
    float s = 0.f;
#pragma unroll
    for (int i = 0; i < 4; i++) {
        int c = tid + i * 128;
        float v = W[k * C_ + c];
        s += v * v;
        float r = tf32r(v);
        g_wr[k * C_ + c] = r;
        g_wt[(size_t)c * K_ + k] = r;
    }
    for (int o = 16; o; o >>= 1) s += __shfl_xor_sync(0xffffffffu, s, o);
    __shared__ float sr[4];
    if ((tid & 31) == 0) sr[tid >> 5] = s;
    __syncthreads();
    if (tid == 0) g_wsq[k] = sr[0] + sr[1] + sr[2] + sr[3];
}

// ---------- downsample: RAW partial sums; split over blockIdx.z ----------
__global__ void downsample_kernel(int pn, int splz) {
    int c = blockIdx.y * 128 + threadIdx.x;
    int m = blockIdx.x;
    if (blockIdx.y == 0 && blockIdx.z == 0 && threadIdx.x == 0) g_S[m] = 0.f;
    int b = m / pn;
    int j = m - b * pn;
    int L = N_ / pn;
    int Lc = L / splz;
    int nb = blockIdx.z * Lc;
    const float* src = g_frest + ((size_t)b * N_ + (size_t)j * L + nb) * C_ + c;
    float s0 = 0.f, s1 = 0.f, s2 = 0.f, s3 = 0.f;
    int n = 0;
    for (; n + 4 <= Lc; n += 4) {
        s0 += src[(n + 0) * C_];
        s1 += src[(n + 1) * C_];
        s2 += src[(n + 2) * C_];
        s3 += src[(n + 3) * C_];
    }
    for (; n < Lc; n++) s0 += src[n * C_];
    float s = (s0 + s1 + s2 + s3);
    if (splz > 1) atomicAdd(&g_z[m * C_ + c], s);
    else          g_z[m * C_ + c] = s;
}

// ---------- GEMM config ----------
#define TILE_M 128
#define TILE_N 128
#define BK     32
#define STAGE_FLOATS ((TILE_M + TILE_N) * BK)      // 8192 floats = 32 KB
#define GEMM_SMEM    (2 * STAGE_FLOATS * 4)        // 64 KB

// ---------- GEMM1 + exp fusion: E[m,n] = exp(wsq[n] - 2*sum_k tf32r(zraw*invL)*Wr[n,k]) ----------
__global__ __launch_bounds__(256, 2)
void gemm_exp(const float* __restrict__ A, const float* __restrict__ B,
              float* __restrict__ E, int M, float invL)
{
    extern __shared__ float smem[];
    const int lda = C_, ldb = C_, Ntot = K_, Ktot = C_;
    int tid = threadIdx.x, wid = tid >> 5, lane = tid & 31;
    int m0 = blockIdx.y * TILE_M, n0 = blockIdx.x * TILE_N;
    int wm = wid & 1, wn = wid >> 1;
    uint32_t sbase = smem_u32(smem);

    float acc[4][4][4];
#pragma unroll
    for (int i = 0; i < 4; i++)
#pragma unroll
        for (int j = 0; j < 4; j++)
#pragma unroll
            for (int q = 0; q < 4; q++) acc[i][j][q] = 0.f;

    int ld_r = tid >> 3;
    int ld_u = tid & 7;
    int arow = wm * 64 + (lane & 15);
    int ahk  = (lane >> 4) & 1;
    int brow = wn * 32 + (lane & 7) + ((lane & 16) ? 8 : 0);
    int sw   = lane & 7;
    int NS = Ktot / BK;

    int arow_g[4];
#pragma unroll
    for (int i = 0; i < 4; i++) arow_g[i] = min(m0 + ld_r + i * 32, M - 1);

    float4 areg[4];
    auto ldgA = [&](int kt) {
#pragma unroll
        for (int i = 0; i < 4; i++)
            areg[i] = *(const float4*)(A + (size_t)arow_g[i] * lda + kt + ld_u * 4);
    };
    auto stsA = [&](int bufsel) {
        char* base = (char*)smem + (size_t)bufsel * (STAGE_FLOATS << 2);
#pragma unroll
        for (int i = 0; i < 4; i++) {
            int r = ld_r + i * 32;
            float4 p;
            p.x = tf32r(__fmul_rn(areg[i].x, invL));
            p.y = tf32r(__fmul_rn(areg[i].y, invL));
            p.z = tf32r(__fmul_rn(areg[i].z, invL));
            p.w = tf32r(__fmul_rn(areg[i].w, invL));
            *(float4*)(base + ((r * 8 + (ld_u ^ (r & 7))) << 4)) = p;
        }
    };
    auto cpB = [&](int kt, int bufsel) {
        uint32_t base = sbase + (uint32_t)bufsel * (STAGE_FLOATS << 2) + ((TILE_M * BK) << 2);
#pragma unroll
        for (int i = 0; i < 4; i++) {
            int r = ld_r + i * 32;
            uint32_t sb2 = base + ((r * 8 + (ld_u ^ (r & 7))) << 4);
            cp_async16(sb2, B + (size_t)(n0 + r) * ldb + kt + ld_u * 4);
        }
        cp_commit();
    };

    ldgA(0);
    cpB(0, 0);
    stsA(0);

    for (int s = 0; s < NS; s++) {
        int cur = s & 1;
        int nxt = 1 - cur;
        if (s + 1 < NS) {
            ldgA((s + 1) * BK);
            cpB((s + 1) * BK, nxt);
            asm volatile("cp.async.wait_group 1;" ::: "memory");
        } else {
            asm volatile("cp.async.wait_group 0;" ::: "memory");
        }
        __syncthreads();

        uint32_t sA = sbase + (uint32_t)cur * (STAGE_FLOATS << 2);
        uint32_t sB = sA + ((TILE_M * BK) << 2);
#pragma unroll
        for (int ks = 0; ks < 4; ks++) {
            uint32_t bfr[4][2];
#pragma unroll
            for (int g = 0; g < 2; g++) {
                uint32_t r4[4];
                int row = brow + g * 16;
                int bhk = (lane >> 3) & 1;
                uint32_t addr = sB + ((row * 8 + ((ks * 2 + bhk) ^ sw)) << 4);
                ldm_x4(r4, addr);
                bfr[2 * g + 0][0] = r4[0]; bfr[2 * g + 0][1] = r4[1];
                bfr[2 * g + 1][0] = r4[2]; bfr[2 * g + 1][1] = r4[3];
            }
#pragma unroll
            for (int mf = 0; mf < 4; mf++) {
                uint32_t afr[4];
                int row = arow + mf * 16;
                uint32_t addr = sA + ((row * 8 + ((ks * 2 + ahk) ^ sw)) << 4);
                ldm_x4(afr, addr);
#pragma unroll
                for (int nf = 0; nf < 4; nf++)
                    mma_tf32(acc[mf][nf], afr, bfr[nf]);
            }
        }
        if (s + 1 < NS) stsA(nxt);
        __syncthreads();
    }

    // ---- epilogue: e = exp(wsq + (-2)*acc); rowsum -> atomic g_S ----
    int er = lane >> 2;
    int ec = (lane & 3) * 2;
#pragma unroll
    for (int mf = 0; mf < 4; mf++) {
#pragma unroll
        for (int half = 0; half < 2; half++) {
            int row = m0 + wm * 64 + mf * 16 + er + half * 8;
            float rs = 0.f;
            if (row < M) {
                float* Erow = E + (size_t)row * Ntot + n0 + wn * 32 + ec;
#pragma unroll
                for (int nf = 0; nf < 4; nf++) {
                    int ncol = n0 + wn * 32 + ec + nf * 8;
                    float e0 = exp_small(__fadd_rn(__fmul_rn(acc[mf][nf][half * 2 + 0], -2.0f),
                                                   g_wsq[ncol]));
                    float e1 = exp_small(__fadd_rn(__fmul_rn(acc[mf][nf][half * 2 + 1], -2.0f),
                                                   g_wsq[ncol + 1]));
                    float2 v; v.x = e0; v.y = e1;
                    *(float2*)(Erow + nf * 8) = v;
                    rs += e0 + e1;
                }
            }
            rs += __shfl_xor_sync(0xffffffffu, rs, 1);
            rs += __shfl_xor_sync(0xffffffffu, rs, 2);
            if ((lane & 3) == 0 && row < M) atomicAdd(&g_S[row], rs);
        }
    }
}

// ---------- GEMM2 + normalize fusion, split-K over blockIdx.z ----------
__global__ __launch_bounds__(256, 2)
void gemm_p(const float* __restrict__ Eg, const float* __restrict__ B,
            float* __restrict__ D, int M, int kchunk, int ksplit)
{
    extern __shared__ float smem[];
    const int lda = K_, ldb = K_, Ntot = C_;
    int tid = threadIdx.x, wid = tid >> 5, lane = tid & 31;
    int m0 = blockIdx.y * TILE_M, n0 = blockIdx.x * TILE_N;
    int k0 = blockIdx.z * kchunk;
    int wm = wid & 1, wn = wid >> 1;
    uint32_t sbase = smem_u32(smem);

    float acc[4][4][4];
#pragma unroll
    for (int i = 0; i < 4; i++)
#pragma unroll
        for (int j = 0; j < 4; j++)
#pragma unroll
            for (int q = 0; q < 4; q++) acc[i][j][q] = 0.f;

    int ld_r = tid >> 3;
    int ld_u = tid & 7;
    int arow = wm * 64 + (lane & 15);
    int ahk  = (lane >> 4) & 1;
    int brow = wn * 32 + (lane & 7) + ((lane & 16) ? 8 : 0);
    int sw   = lane & 7;
    int NS = kchunk / BK;

    int arow_g[4];
    float rinv[4];
#pragma unroll
    for (int i = 0; i < 4; i++) {
        arow_g[i] = min(m0 + ld_r + i * 32, M - 1);
        rinv[i] = __frcp_rn(g_S[arow_g[i]]);
    }

    float4 areg[4];
    auto ldgA = [&](int kt) {
#pragma unroll
        for (int i = 0; i < 4; i++)
            areg[i] = *(const float4*)(Eg + (size_t)arow_g[i] * lda + k0 + kt + ld_u * 4);
    };
    auto stsA = [&](int bufsel) {
        char* base = (char*)smem + (size_t)bufsel * (STAGE_FLOATS << 2);
#pragma unroll
        for (int i = 0; i < 4; i++) {
            int r = ld_r + i * 32;
            float4 p;
            p.x = tf32r(__fmul_rn(areg[i].x, rinv[i]));
            p.y = tf32r(__fmul_rn(areg[i].y, rinv[i]));
            p.z = tf32r(__fmul_rn(areg[i].z, rinv[i]));
            p.w = tf32r(__fmul_rn(areg[i].w, rinv[i]));
            *(float4*)(base + ((r * 8 + (ld_u ^ (r & 7))) << 4)) = p;
        }
    };
    auto cpB = [&](int kt, int bufsel) {
        uint32_t base = sbase + (uint32_t)bufsel * (STAGE_FLOATS << 2) + ((TILE_M * BK) << 2);
#pragma unroll
        for (int i = 0; i < 4; i++) {
            int r = ld_r + i * 32;
            uint32_t sb2 = base + ((r * 8 + (ld_u ^ (r & 7))) << 4);
            cp_async16(sb2, B + (size_t)(n0 + r) * ldb + k0 + kt + ld_u * 4);
        }
        cp_commit();
    };

    ldgA(0);
    cpB(0, 0);
    stsA(0);

    for (int s = 0; s < NS; s++) {
        int cur = s & 1;
        int nxt = 1 - cur;
        if (s + 1 < NS) {
            ldgA((s + 1) * BK);
            cpB((s + 1) * BK, nxt);
            asm volatile("cp.async.wait_group 1;" ::: "memory");
        } else {
            asm volatile("cp.async.wait_group 0;" ::: "memory");
        }
        __syncthreads();

        uint32_t sA = sbase + (uint32_t)cur * (STAGE_FLOATS << 2);
        uint32_t sB = sA + ((TILE_M * BK) << 2);
#pragma unroll
        for (int ks = 0; ks < 4; ks++) {
            uint32_t bfr[4][2];
#pragma unroll
            for (int g = 0; g < 2; g++) {
                uint32_t r4[4];
                int row = brow + g * 16;
                int bhk = (lane >> 3) & 1;
                uint32_t addr = sB + ((row * 8 + ((ks * 2 + bhk) ^ sw)) << 4);
                ldm_x4(r4, addr);
                bfr[2 * g + 0][0] = r4[0]; bfr[2 * g + 0][1] = r4[1];
                bfr[2 * g + 1][0] = r4[2]; bfr[2 * g + 1][1] = r4[3];
            }
#pragma unroll
            for (int mf = 0; mf < 4; mf++) {
                uint32_t afr[4];
                int row = arow + mf * 16;
                uint32_t addr = sA + ((row * 8 + ((ks * 2 + ahk) ^ sw)) << 4);
                ldm_x4(afr, addr);
#pragma unroll
                for (int nf = 0; nf < 4; nf++)
                    mma_tf32(acc[mf][nf], afr, bfr[nf]);
            }
        }
        if (s + 1 < NS) stsA(nxt);
        __syncthreads();
    }

    // ---- epilogue: store or atomic-accumulate ----
    int er = lane >> 2;
    int ec = (lane & 3) * 2;
#pragma unroll
    for (int mf = 0; mf < 4; mf++) {
#pragma unroll
        for (int half = 0; half < 2; half++) {
            int row = m0 + wm * 64 + mf * 16 + er + half * 8;
            if (row < M) {
                float* Drow = D + (size_t)row * Ntot + n0 + wn * 32 + ec;
                if (ksplit > 1) {
#pragma unroll
                    for (int nf = 0; nf < 4; nf++) {
                        atomicAdd(Drow + nf * 8 + 0, acc[mf][nf][half * 2 + 0]);
                        atomicAdd(Drow + nf * 8 + 1, acc[mf][nf][half * 2 + 1]);
                    }
                } else {
#pragma unroll
                    for (int nf = 0; nf < 4; nf++) {
                        float2 v;
                        v.x = acc[mf][nf][half * 2 + 0];
                        v.y = acc[mf][nf][half * 2 + 1];
                        *(float2*)(Drow + nf * 8) = v;
                    }
                }
            }
        }
    }
}

// ---------- upsample + f_hat/f_rest update + loss accum (+ final out) ----------
__global__ void update_kernel(const float* __restrict__ f, float* __restrict__ out,
                              int pn, int last)
{
    int i4 = blockIdx.x * blockDim.x + threadIdx.x;
    int idx = i4 << 2;
    int c = idx & (C_ - 1);
    int n = (idx >> 9) & (N_ - 1);
    int b = idx >> 19;

    float scale = (float)pn / (float)N_;
    float coord = __fsub_rn(__fmul_rn((float)n + 0.5f, scale), 0.5f);
    coord = fminf(fmaxf(coord, 0.0f), (float)(pn - 1));
    int i0 = (int)floorf(coord);
    int i1 = min(i0 + 1, pn - 1);
    float w = __fsub_rn(coord, (float)i0);
    float om = __fsub_rn(1.0f, w);

    const float* h0 = g_h + (size_t)(b * pn + i0) * C_ + c;
    const float* h1 = g_h + (size_t)(b * pn + i1) * C_ + c;
    float4 ha = *(const float4*)h0;
    float4 hb = *(const float4*)h1;
    float4 fh = *(const float4*)(g_fhat + idx);
    float4 fr = *(const float4*)(g_frest + idx);
    float4 fv = *(const float4*)(f + idx);

    float up0 = __fadd_rn(__fmul_rn(ha.x, om), __fmul_rn(hb.x, w));
    float up1 = __fadd_rn(__fmul_rn(ha.y, om), __fmul_rn(hb.y, w));
    float up2 = __fadd_rn(__fmul_rn(ha.z, om), __fmul_rn(hb.z, w));
    float up3 = __fadd_rn(__fmul_rn(ha.w, om), __fmul_rn(hb.w, w));

    fh.x = __fadd_rn(fh.x, up0); fh.y = __fadd_rn(fh.y, up1);
    fh.z = __fadd_rn(fh.z, up2); fh.w = __fadd_rn(fh.w, up3);
    fr.x = __fsub_rn(fr.x, up0); fr.y = __fsub_rn(fr.y, up1);
    fr.z = __fsub_rn(fr.z, up2); fr.w = __fsub_rn(fr.w, up3);
    *(float4*)(g_fhat + idx) = fh;
    *(float4*)(g_frest + idx) = fr;

    float t0 = __fsub_rn(fh.x, fv.x);
    float t1 = __fsub_rn(fh.y, fv.y);
    float t2 = __fsub_rn(fh.z, fv.z);
    float t3 = __fsub_rn(fh.w, fv.w);

    float sq = t0 * t0 + t1 * t1 + t2 * t2 + t3 * t3;

    if (last) {
        float4 o = make_float4(__fadd_rn(t0, fv.x), __fadd_rn(t1, fv.y),
                               __fadd_rn(t2, fv.z), __fadd_rn(t3, fv.w));
        *(float4*)(out + idx) = o;
    }

    for (int o = 16; o; o >>= 1) sq += __shfl_xor_sync(0xffffffffu, sq, o);
    __shared__ float sred[8];
    int tid = threadIdx.x;
    if ((tid & 31) == 0) sred[tid >> 5] = sq;
    __syncthreads();
    if (tid == 0) {
        float t = sred[0] + sred[1] + sred[2] + sred[3] +
                  sred[4] + sred[5] + sred[6] + sred[7];
        atomicAdd(&g_sum, (double)t);
    }
}

// ---------- scalars ----------
__global__ void finalize_kernel(float* __restrict__ out) {
    double mean = g_sum / ((double)TOT * (double)NSCALES);
    out[TOT]     = (float)(0.25 * mean);   // commit
    out[TOT + 1] = (float)mean;            // qlat
}

extern "C" void kernel_launch(void* const* d_in, const int* in_sizes, int n_in,
                              void* d_out, int out_size)
{
    const float* f = (const float*)d_in[0];   // (B, N, C) fp32
    const float* W = (const float*)d_in[1];   // (K, C)    fp32
    float* out = (float*)d_out;

    float *zp = nullptr, *ep = nullptr, *hp = nullptr, *wr = nullptr, *wt = nullptr;
    cudaGetSymbolAddress((void**)&zp, g_z);
    cudaGetSymbolAddress((void**)&ep, g_e);
    cudaGetSymbolAddress((void**)&hp, g_h);
    cudaGetSymbolAddress((void**)&wr, g_wr);
    cudaGetSymbolAddress((void**)&wt, g_wt);

    cudaFuncSetAttribute(gemm_exp, cudaFuncAttributeMaxDynamicSharedMemorySize, GEMM_SMEM);
    cudaFuncSetAttribute(gemm_p,   cudaFuncAttributeMaxDynamicSharedMemorySize, GEMM_SMEM);

    init_copy<<<TOT / 4 / 256, 256>>>(f);
    prep_w<<<K_, 128>>>(W);

    for (int s = 0; s < NSCALES; s++) {
        int pn = 1 << s;
        int M = B_ * pn;
        int L = N_ / pn;
        int mt = (M + TILE_M - 1) / TILE_M;

        // ---- downsample (split reduction when M small) ----
        int splz = 512 / M;          // target ~2K blocks
        if (splz < 1) splz = 1;
        if (splz > L) splz = L;
        if (splz > 1)
            cudaMemsetAsync(zp, 0, (size_t)M * C_ * sizeof(float));
        downsample_kernel<<<dim3(M, C_ / 128, splz), 128>>>(pn, splz);

        // ---- E = exp(wsq - 2 tf32r(zraw/L) Wr^T), rowsums in g_S ----
        gemm_exp<<<dim3(K_ / TILE_N, mt), 256, GEMM_SMEM>>>(zp, wr, ep, M, 1.0f / (float)L);

        // ---- h = tf32r(E/S) @ W, split-K when M small ----
        int ksplit = (M <= 2048) ? 8 : 1;
        int kchunk = K_ / ksplit;
        if (ksplit > 1)
            cudaMemsetAsync(hp, 0, (size_t)M * C_ * sizeof(float));
        gemm_p<<<dim3(C_ / TILE_N, mt, ksplit), 256, GEMM_SMEM>>>(ep, wt, hp, M, kchunk, ksplit);

        update_kernel<<<TOT / 4 / 256, 256>>>(f, out, pn, s == NSCALES - 1 ? 1 : 0);
    }
    finalize_kernel<<<1, 1>>>(out);
}

// round 10
// speedup vs baseline: 1.3388x; 1.0198x over previous
#include <cuda_runtime.h>
#include <cuda_bf16.h>
#include <math.h>
#include <stdint.h>

#define B_      32
#define N_      1024
#define C_      512
#define K_      4096
#define NSCALES 11
#define TOT     (B_*N_*C_)      // 16777216
#define MMAX    (B_*1024)       // 32768

// ---------- static device scratch ----------
__device__ float  g_frest[TOT];
__device__ float  g_fhat[TOT];
__device__ float  g_z[MMAX * C_];            // RAW block sums (scaled at gemm A-load)
__device__ float  g_e[(size_t)MMAX * K_];    // exp(d) (pre-normalization)
__device__ float  g_h[MMAX * C_];
__device__ float  g_wr[K_ * C_];             // tf32-rounded W   (4096 x 512)
__device__ float  g_wt[C_ * K_];             // tf32-rounded W^T (512 x 4096)
__device__ float  g_wsq[K_];
__device__ float  g_S[MMAX];                 // softmax row sums
__device__ double g_sum;

// ---------- helpers ----------
__device__ __forceinline__ float tf32r(float x) {
    float y;
    asm("cvt.rna.tf32.f32 %0, %1;" : "=f"(y) : "f"(x));
    return y;
}
__device__ __forceinline__ uint32_t smem_u32(const void* p) {
    uint32_t a;
    asm("{ .reg .u64 t; cvta.to.shared.u64 t, %1; cvt.u32.u64 %0, t; }" : "=r"(a) : "l"(p));
    return a;
}
__device__ __forceinline__ void cp_async16(uint32_t saddr, const void* gaddr) {
    asm volatile("cp.async.cg.shared.global [%0], [%1], 16;" :: "r"(saddr), "l"(gaddr));
}
__device__ __forceinline__ void cp_commit() {
    asm volatile("cp.async.commit_group;" ::: "memory");
}
__device__ __forceinline__ void ldm_x4(uint32_t* r, uint32_t addr) {
    asm volatile("ldmatrix.sync.aligned.m8n8.x4.shared.b16 {%0,%1,%2,%3}, [%4];"
                 : "=r"(r[0]), "=r"(r[1]), "=r"(r[2]), "=r"(r[3]) : "r"(addr));
}
__device__ __forceinline__ void mma_tf32(float* d, const uint32_t* a, const uint32_t* b) {
    asm volatile(
        "mma.sync.aligned.m16n8k8.row.col.f32.tf32.tf32.f32 "
        "{%0,%1,%2,%3}, {%4,%5,%6,%7}, {%8,%9}, {%0,%1,%2,%3};"
        : "+f"(d[0]), "+f"(d[1]), "+f"(d[2]), "+f"(d[3])
        : "r"(a[0]), "r"(a[1]), "r"(a[2]), "r"(a[3]), "r"(b[0]), "r"(b[1]));
}
// exp(y) for |y| <= 0.25 via degree-6 Taylor; guarded exact fallback.
__device__ __forceinline__ float exp_small(float y) {
    if (__builtin_expect(fabsf(y) > 0.25f, 0)) return expf(y);
    float t = 1.388888889e-3f;
    t = __fmaf_rn(t, y, 8.333333333e-3f);
    t = __fmaf_rn(t, y, 4.166666667e-2f);
    t = __fmaf_rn(t, y, 1.666666667e-1f);
    t = __fmaf_rn(t, y, 0.5f);
    t = __fmaf_rn(t, y, 1.0f);
    t = __fmaf_rn(t, y, 1.0f);
    return t;
}

// ---------- init ----------
__global__ void init_copy(const float* __restrict__ f) {
    int i = blockIdx.x * blockDim.x + threadIdx.x;
    ((float4*)g_frest)[i] = ((const float4*)f)[i];
    ((float4*)g_fhat)[i] = make_float4(0.f, 0.f, 0.f, 0.f);
    if (i == 0) g_sum = 0.0;
}

// ---------- prep: w_sq (raw W) + tf32-rounded W and W^T ----------
__global__ void prep_w(const float* __restrict__ W) {
    int k = blockIdx.x;
    int tid = threadIdx.x;                           // 128 threads
    float s = 0.f;
#pragma unroll
    for (int i = 0; i < 4; i++) {
        int c = tid + i * 128;
        float v = W[k * C_ + c];
        s += v * v;
        float r = tf32r(v);
        g_wr[k * C_ + c] = r;
        g_wt[(size_t)c * K_ + k] = r;
    }
    for (int o = 16; o; o >>= 1) s += __shfl_xor_sync(0xffffffffu, s, o);
    __shared__ float sr[4];
    if ((tid & 31) == 0) sr[tid >> 5] = s;
    __syncthreads();
    if (tid == 0) g_wsq[k] = sr[0] + sr[1] + sr[2] + sr[3];
}

// ---------- downsample: RAW partial sums; split over blockIdx.z ----------
__global__ void downsample_kernel(int pn, int splz) {
    int c = blockIdx.y * 128 + threadIdx.x;
    int m = blockIdx.x;
    if (blockIdx.y == 0 && blockIdx.z == 0 && threadIdx.x == 0) g_S[m] = 0.f;
    int b = m / pn;
    int j = m - b * pn;
    int L = N_ / pn;
    int Lc = L / splz;
    int nb = blockIdx.z * Lc;
    const float* src = g_frest + ((size_t)b * N_ + (size_t)j * L + nb) * C_ + c;
    float s0 = 0.f, s1 = 0.f, s2 = 0.f, s3 = 0.f;
    int n = 0;
    for (; n + 4 <= Lc; n += 4) {
        s0 += src[(n + 0) * C_];
        s1 += src[(n + 1) * C_];
        s2 += src[(n + 2) * C_];
        s3 += src[(n + 3) * C_];
    }
    for (; n < Lc; n++) s0 += src[n * C_];
    float s = (s0 + s1 + s2 + s3);
    if (splz > 1) atomicAdd(&g_z[m * C_ + c], s);
    else          g_z[m * C_ + c] = s;
}

// ---------- GEMM config: 128x128 CTA tile, 128 threads (4 warps 2x2), warp tile 64x64 ----------
#define TILE_M 128
#define TILE_N 128
#define BK     32
#define GTHREADS 128
#define STAGE_FLOATS ((TILE_M + TILE_N) * BK)      // 8192 floats = 32 KB
#define GEMM_SMEM    (2 * STAGE_FLOATS * 4)        // 64 KB

// ---------- GEMM1 + exp fusion: E[m,n] = exp(wsq[n] - 2*sum_k tf32r(zraw*invL)*Wr[n,k]) ----------
__global__ __launch_bounds__(GTHREADS, 2)
void gemm_exp(const float* __restrict__ A, const float* __restrict__ B,
              float* __restrict__ E, int M, float invL)
{
    extern __shared__ float smem[];
    const int lda = C_, ldb = C_, Ntot = K_, Ktot = C_;
    int tid = threadIdx.x, wid = tid >> 5, lane = tid & 31;
    int m0 = blockIdx.y * TILE_M, n0 = blockIdx.x * TILE_N;
    int wm = wid & 1, wn = wid >> 1;           // 2(M) x 2(N)
    uint32_t sbase = smem_u32(smem);

    float acc[4][8][4];
#pragma unroll
    for (int i = 0; i < 4; i++)
#pragma unroll
        for (int j = 0; j < 8; j++)
#pragma unroll
            for (int q = 0; q < 4; q++) acc[i][j][q] = 0.f;

    int ld_r8 = tid >> 3;          // 0..15
    int ld_u  = tid & 7;
    int arow = wm * 64 + (lane & 15);
    int ahk  = (lane >> 4) & 1;
    int brow_b = wn * 64 + (lane & 7) + ((lane & 16) ? 8 : 0);
    int bhk  = (lane >> 3) & 1;
    int sw   = lane & 7;
    int NS = Ktot / BK;

    int arow_g[8];
#pragma unroll
    for (int i = 0; i < 8; i++) arow_g[i] = min(m0 + i * 16 + ld_r8, M - 1);

    float4 areg[8];
    auto ldgA = [&](int kt) {
#pragma unroll
        for (int i = 0; i < 8; i++)
            areg[i] = *(const float4*)(A + (size_t)arow_g[i] * lda + kt + ld_u * 4);
    };
    auto stsA = [&](int bufsel) {
        char* base = (char*)smem + (size_t)bufsel * (STAGE_FLOATS << 2);
#pragma unroll
        for (int i = 0; i < 8; i++) {
            int r = i * 16 + ld_r8;
            float4 p;
            p.x = tf32r(__fmul_rn(areg[i].x, invL));
            p.y = tf32r(__fmul_rn(areg[i].y, invL));
            p.z = tf32r(__fmul_rn(areg[i].z, invL));
            p.w = tf32r(__fmul_rn(areg[i].w, invL));
            *(float4*)(base + ((r * 8 + (ld_u ^ (r & 7))) << 4)) = p;
        }
    };
    auto cpB = [&](int kt, int bufsel) {
        uint32_t base = sbase + (uint32_t)bufsel * (STAGE_FLOATS << 2) + ((TILE_M * BK) << 2);
#pragma unroll
        for (int i = 0; i < 8; i++) {
            int r = i * 16 + ld_r8;
            uint32_t sb2 = base + ((r * 8 + (ld_u ^ (r & 7))) << 4);
            cp_async16(sb2, B + (size_t)(n0 + r) * ldb + kt + ld_u * 4);
        }
        cp_commit();
    };

    ldgA(0);
    cpB(0, 0);
    stsA(0);

    for (int s = 0; s < NS; s++) {
        int cur = s & 1;
        int nxt = 1 - cur;
        if (s + 1 < NS) {
            ldgA((s + 1) * BK);
            cpB((s + 1) * BK, nxt);
            asm volatile("cp.async.wait_group 1;" ::: "memory");
        } else {
            asm volatile("cp.async.wait_group 0;" ::: "memory");
        }
        __syncthreads();

        uint32_t sA = sbase + (uint32_t)cur * (STAGE_FLOATS << 2);
        uint32_t sB = sA + ((TILE_M * BK) << 2);
#pragma unroll
        for (int ks = 0; ks < 4; ks++) {
            uint32_t bfr[8][2];
#pragma unroll
            for (int g = 0; g < 4; g++) {
                uint32_t r4[4];
                int row = brow_b + g * 16;
                int unit = ks * 2 + bhk;
                uint32_t addr = sB + ((row * 8 + (unit ^ (row & 7))) << 4);
                ldm_x4(r4, addr);
                bfr[2 * g + 0][0] = r4[0]; bfr[2 * g + 0][1] = r4[1];
                bfr[2 * g + 1][0] = r4[2]; bfr[2 * g + 1][1] = r4[3];
            }
#pragma unroll
            for (int mf = 0; mf < 4; mf++) {
                uint32_t afr[4];
                int row = arow + mf * 16;
                int unit = ks * 2 + ahk;
                uint32_t addr = sA + ((row * 8 + (unit ^ (row & 7))) << 4);
                ldm_x4(afr, addr);
#pragma unroll
                for (int nf = 0; nf < 8; nf++)
                    mma_tf32(acc[mf][nf], afr, bfr[nf]);
            }
        }
        if (s + 1 < NS) stsA(nxt);
        __syncthreads();
    }

    // ---- epilogue: e = exp(wsq + (-2)*acc); rowsum -> atomic g_S ----
    int er = lane >> 2;
    int ec = (lane & 3) * 2;
#pragma unroll
    for (int mf = 0; mf < 4; mf++) {
#pragma unroll
        for (int half = 0; half < 2; half++) {
            int row = m0 + wm * 64 + mf * 16 + er + half * 8;
            float rs = 0.f;
            if (row < M) {
                float* Erow = E + (size_t)row * Ntot + n0 + wn * 64 + ec;
#pragma unroll
                for (int nf = 0; nf < 8; nf++) {
                    int ncol = n0 + wn * 64 + ec + nf * 8;
                    float e0 = exp_small(__fadd_rn(__fmul_rn(acc[mf][nf][half * 2 + 0], -2.0f),
                                                   g_wsq[ncol]));
                    float e1 = exp_small(__fadd_rn(__fmul_rn(acc[mf][nf][half * 2 + 1], -2.0f),
                                                   g_wsq[ncol + 1]));
                    float2 v; v.x = e0; v.y = e1;
                    *(float2*)(Erow + nf * 8) = v;
                    rs += e0 + e1;
                }
            }
            rs += __shfl_xor_sync(0xffffffffu, rs, 1);
            rs += __shfl_xor_sync(0xffffffffu, rs, 2);
            if ((lane & 3) == 0 && row < M) atomicAdd(&g_S[row], rs);
        }
    }
}

// ---------- GEMM2 + normalize fusion, split-K over blockIdx.z ----------
__global__ __launch_bounds__(GTHREADS, 2)
void gemm_p(const float* __restrict__ Eg, const float* __restrict__ B,
            float* __restrict__ D, int M, int kchunk, int ksplit)
{
    extern __shared__ float smem[];
    const int lda = K_, ldb = K_, Ntot = C_;
    int tid = threadIdx.x, wid = tid >> 5, lane = tid & 31;
    int m0 = blockIdx.y * TILE_M, n0 = blockIdx.x * TILE_N;
    int k0 = blockIdx.z * kchunk;
    int wm = wid & 1, wn = wid >> 1;
    uint32_t sbase = smem_u32(smem);

    float acc[4][8][4];
#pragma unroll
    for (int i = 0; i < 4; i++)
#pragma unroll
        for (int j = 0; j < 8; j++)
#pragma unroll
            for (int q = 0; q < 4; q++) acc[i][j][q] = 0.f;

    int ld_r8 = tid >> 3;
    int ld_u  = tid & 7;
    int arow = wm * 64 + (lane & 15);
    int ahk  = (lane >> 4) & 1;
    int brow_b = wn * 64 + (lane & 7) + ((lane & 16) ? 8 : 0);
    int bhk  = (lane >> 3) & 1;
    int sw   = lane & 7;
    int NS = kchunk / BK;

    int arow_g[8];
    float rinv[8];
#pragma unroll
    for (int i = 0; i < 8; i++) {
        arow_g[i] = min(m0 + i * 16 + ld_r8, M - 1);
        rinv[i] = __frcp_rn(g_S[arow_g[i]]);
    }

    float4 areg[8];
    auto ldgA = [&](int kt) {
#pragma unroll
        for (int i = 0; i < 8; i++)
            areg[i] = *(const float4*)(Eg + (size_t)arow_g[i] * lda + k0 + kt + ld_u * 4);
    };
    auto stsA = [&](int bufsel) {
        char* base = (char*)smem + (size_t)bufsel * (STAGE_FLOATS << 2);
#pragma unroll
        for (int i = 0; i < 8; i++) {
            int r = i * 16 + ld_r8;
            float4 p;
            p.x = tf32r(__fmul_rn(areg[i].x, rinv[i]));
            p.y = tf32r(__fmul_rn(areg[i].y, rinv[i]));
            p.z = tf32r(__fmul_rn(areg[i].z, rinv[i]));
            p.w = tf32r(__fmul_rn(areg[i].w, rinv[i]));
            *(float4*)(base + ((r * 8 + (ld_u ^ (r & 7))) << 4)) = p;
        }
    };
    auto cpB = [&](int kt, int bufsel) {
        uint32_t base = sbase + (uint32_t)bufsel * (STAGE_FLOATS << 2) + ((TILE_M * BK) << 2);
#pragma unroll
        for (int i = 0; i < 8; i++) {
            int r = i * 16 + ld_r8;
            uint32_t sb2 = base + ((r * 8 + (ld_u ^ (r & 7))) << 4);
            cp_async16(sb2, B + (size_t)(n0 + r) * ldb + k0 + kt + ld_u * 4);
        }
        cp_commit();
    };

    ldgA(0);
    cpB(0, 0);
    stsA(0);

    for (int s = 0; s < NS; s++) {
        int cur = s & 1;
        int nxt = 1 - cur;
        if (s + 1 < NS) {
            ldgA((s + 1) * BK);
            cpB((s + 1) * BK, nxt);
            asm volatile("cp.async.wait_group 1;" ::: "memory");
        } else {
            asm volatile("cp.async.wait_group 0;" ::: "memory");
        }
        __syncthreads();

        uint32_t sA = sbase + (uint32_t)cur * (STAGE_FLOATS << 2);
        uint32_t sB = sA + ((TILE_M * BK) << 2);
#pragma unroll
        for (int ks = 0; ks < 4; ks++) {
            uint32_t bfr[8][2];
#pragma unroll
            for (int g = 0; g < 4; g++) {
                uint32_t r4[4];
                int row = brow_b + g * 16;
                int unit = ks * 2 + bhk;
                uint32_t addr = sB + ((row * 8 + (unit ^ (row & 7))) << 4);
                ldm_x4(r4, addr);
                bfr[2 * g + 0][0] = r4[0]; bfr[2 * g + 0][1] = r4[1];
                bfr[2 * g + 1][0] = r4[2]; bfr[2 * g + 1][1] = r4[3];
            }
#pragma unroll
            for (int mf = 0; mf < 4; mf++) {
                uint32_t afr[4];
                int row = arow + mf * 16;
                int unit = ks * 2 + ahk;
                uint32_t addr = sA + ((row * 8 + (unit ^ (row & 7))) << 4);
                ldm_x4(afr, addr);
#pragma unroll
                for (int nf = 0; nf < 8; nf++)
                    mma_tf32(acc[mf][nf], afr, bfr[nf]);
            }
        }
        if (s + 1 < NS) stsA(nxt);
        __syncthreads();
    }

    // ---- epilogue: store or atomic-accumulate ----
    int er = lane >> 2;
    int ec = (lane & 3) * 2;
#pragma unroll
    for (int mf = 0; mf < 4; mf++) {
#pragma unroll
        for (int half = 0; half < 2; half++) {
            int row = m0 + wm * 64 + mf * 16 + er + half * 8;
            if (row < M) {
                float* Drow = D + (size_t)row * Ntot + n0 + wn * 64 + ec;
                if (ksplit > 1) {
#pragma unroll
                    for (int nf = 0; nf < 8; nf++) {
                        atomicAdd(Drow + nf * 8 + 0, acc[mf][nf][half * 2 + 0]);
                        atomicAdd(Drow + nf * 8 + 1, acc[mf][nf][half * 2 + 1]);
                    }
                } else {
#pragma unroll
                    for (int nf = 0; nf < 8; nf++) {
                        float2 v;
                        v.x = acc[mf][nf][half * 2 + 0];
                        v.y = acc[mf][nf][half * 2 + 1];
                        *(float2*)(Drow + nf * 8) = v;
                    }
                }
            }
        }
    }
}

// ---------- upsample + f_hat/f_rest update + loss accum (+ final out) ----------
__global__ void update_kernel(const float* __restrict__ f, float* __restrict__ out,
                              int pn, int last)
{
    int i4 = blockIdx.x * blockDim.x + threadIdx.x;
    int idx = i4 << 2;
    int c = idx & (C_ - 1);
    int n = (idx >> 9) & (N_ - 1);
    int b = idx >> 19;

    float scale = (float)pn / (float)N_;
    float coord = __fsub_rn(__fmul_rn((float)n + 0.5f, scale), 0.5f);
    coord = fminf(fmaxf(coord, 0.0f), (float)(pn - 1));
    int i0 = (int)floorf(coord);
    int i1 = min(i0 + 1, pn - 1);
    float w = __fsub_rn(coord, (float)i0);
    float om = __fsub_rn(1.0f, w);

    const float* h0 = g_h + (size_t)(b * pn + i0) * C_ + c;
    const float* h1 = g_h + (size_t)(b * pn + i1) * C_ + c;
    float4 ha = *(const float4*)h0;
    float4 hb = *(const float4*)h1;
    float4 fh = *(const float4*)(g_fhat + idx);
    float4 fr = *(const float4*)(g_frest + idx);
    float4 fv = *(const float4*)(f + idx);

    float up0 = __fadd_rn(__fmul_rn(ha.x, om), __fmul_rn(hb.x, w));
    float up1 = __fadd_rn(__fmul_rn(ha.y, om), __fmul_rn(hb.y, w));
    float up2 = __fadd_rn(__fmul_rn(ha.z, om), __fmul_rn(hb.z, w));
    float up3 = __fadd_rn(__fmul_rn(ha.w, om), __fmul_rn(hb.w, w));

    fh.x = __fadd_rn(fh.x, up0); fh.y = __fadd_rn(fh.y, up1);
    fh.z = __fadd_rn(fh.z, up2); fh.w = __fadd_rn(fh.w, up3);
    fr.x = __fsub_rn(fr.x, up0); fr.y = __fsub_rn(fr.y, up1);
    fr.z = __fsub_rn(fr.z, up2); fr.w = __fsub_rn(fr.w, up3);
    *(float4*)(g_fhat + idx) = fh;
    *(float4*)(g_frest + idx) = fr;

    float t0 = __fsub_rn(fh.x, fv.x);
    float t1 = __fsub_rn(fh.y, fv.y);
    float t2 = __fsub_rn(fh.z, fv.z);
    float t3 = __fsub_rn(fh.w, fv.w);

    float sq = t0 * t0 + t1 * t1 + t2 * t2 + t3 * t3;

    if (last) {
        float4 o = make_float4(__fadd_rn(t0, fv.x), __fadd_rn(t1, fv.y),
                               __fadd_rn(t2, fv.z), __fadd_rn(t3, fv.w));
        *(float4*)(out + idx) = o;
    }

    for (int o = 16; o; o >>= 1) sq += __shfl_xor_sync(0xffffffffu, sq, o);
    __shared__ float sred[8];
    int tid = threadIdx.x;
    if ((tid & 31) == 0) sred[tid >> 5] = sq;
    __syncthreads();
    if (tid == 0) {
        float t = sred[0] + sred[1] + sred[2] + sred[3] +
                  sred[4] + sred[5] + sred[6] + sred[7];
        atomicAdd(&g_sum, (double)t);
    }
}

// ---------- scalars ----------
__global__ void finalize_kernel(float* __restrict__ out) {
    double mean = g_sum / ((double)TOT * (double)NSCALES);
    out[TOT]     = (float)(0.25 * mean);   // commit
    out[TOT + 1] = (float)mean;            // qlat
}

extern "C" void kernel_launch(void* const* d_in, const int* in_sizes, int n_in,
                              void* d_out, int out_size)
{
    const float* f = (const float*)d_in[0];   // (B, N, C) fp32
    const float* W = (const float*)d_in[1];   // (K, C)    fp32
    float* out = (float*)d_out;

    float *zp = nullptr, *ep = nullptr, *hp = nullptr, *wr = nullptr, *wt = nullptr;
    cudaGetSymbolAddress((void**)&zp, g_z);
    cudaGetSymbolAddress((void**)&ep, g_e);
    cudaGetSymbolAddress((void**)&hp, g_h);
    cudaGetSymbolAddress((void**)&wr, g_wr);
    cudaGetSymbolAddress((void**)&wt, g_wt);

    cudaFuncSetAttribute(gemm_exp, cudaFuncAttributeMaxDynamicSharedMemorySize, GEMM_SMEM);
    cudaFuncSetAttribute(gemm_p,   cudaFuncAttributeMaxDynamicSharedMemorySize, GEMM_SMEM);

    init_copy<<<TOT / 4 / 256, 256>>>(f);
    prep_w<<<K_, 128>>>(W);

    for (int s = 0; s < NSCALES; s++) {
        int pn = 1 << s;
        int M = B_ * pn;
        int L = N_ / pn;
        int mt = (M + TILE_M - 1) / TILE_M;

        // ---- downsample (split reduction when M small) ----
        int splz = 512 / M;
        if (splz < 1) splz = 1;
        if (splz > L) splz = L;
        if (splz > 1)
            cudaMemsetAsync(zp, 0, (size_t)M * C_ * sizeof(float));
        downsample_kernel<<<dim3(M, C_ / 128, splz), 128>>>(pn, splz);

        // ---- E = exp(wsq - 2 tf32r(zraw/L) Wr^T), rowsums in g_S ----
        gemm_exp<<<dim3(K_ / TILE_N, mt), GTHREADS, GEMM_SMEM>>>(zp, wr, ep, M, 1.0f / (float)L);

        // ---- h = tf32r(E/S) @ W, split-K when M small ----
        int ksplit = (M <= 2048) ? 8 : 1;
        int kchunk = K_ / ksplit;
        if (ksplit > 1)
            cudaMemsetAsync(hp, 0, (size_t)M * C_ * sizeof(float));
        gemm_p<<<dim3(C_ / TILE_N, mt, ksplit), GTHREADS, GEMM_SMEM>>>(ep, wt, hp, M, kchunk, ksplit);

        update_kernel<<<TOT / 4 / 256, 256>>>(f, out, pn, s == NSCALES - 1 ? 1 : 0);
    }
    finalize_kernel<<<1, 1>>>(out);
}

// round 11
// speedup vs baseline: 1.8488x; 1.3810x over previous
#include <cuda_runtime.h>
#include <cuda_bf16.h>
#include <math.h>
#include <stdint.h>

#define B_      32
#define N_      1024
#define C_      512
#define K_      4096
#define NSCALES 11
#define TOT     (B_*N_*C_)      // 16777216
#define MMAX    (B_*1024)       // 32768

// ---------- static device scratch ----------
__device__ float          g_frest[TOT];
__device__ float          g_fhat[TOT];
__device__ float          g_z[MMAX * C_];          // fp32 partials (split reduction only)
__device__ __nv_bfloat16  g_zb[MMAX * C_];         // bf16 z (GEMM1 A operand)
__device__ __nv_bfloat16  g_u[(size_t)MMAX * K_];  // u = expm1(d), bf16
__device__ float          g_h[MMAX * C_];
__device__ __nv_bfloat16  g_wrb[K_ * C_];          // bf16 W    (4096 x 512)
__device__ __nv_bfloat16  g_wtb[C_ * K_];          // bf16 W^T  (512 x 4096)
__device__ float          g_colsum[C_];            // sum_k tf32r(W[k,c])
__device__ float          g_wsq[K_];
__device__ float          g_S[MMAX];               // row sums of u
__device__ double         g_sum;

// ---------- helpers ----------
__device__ __forceinline__ float tf32r(float x) {
    float y;
    asm("cvt.rna.tf32.f32 %0, %1;" : "=f"(y) : "f"(x));
    return y;
}
__device__ __forceinline__ uint32_t smem_u32(const void* p) {
    uint32_t a;
    asm("{ .reg .u64 t; cvta.to.shared.u64 t, %1; cvt.u32.u64 %0, t; }" : "=r"(a) : "l"(p));
    return a;
}
__device__ __forceinline__ void cp_async16(uint32_t saddr, const void* gaddr) {
    asm volatile("cp.async.cg.shared.global [%0], [%1], 16;" :: "r"(saddr), "l"(gaddr));
}
__device__ __forceinline__ void cp_commit() {
    asm volatile("cp.async.commit_group;" ::: "memory");
}
__device__ __forceinline__ void ldm_x4(uint32_t* r, uint32_t addr) {
    asm volatile("ldmatrix.sync.aligned.m8n8.x4.shared.b16 {%0,%1,%2,%3}, [%4];"
                 : "=r"(r[0]), "=r"(r[1]), "=r"(r[2]), "=r"(r[3]) : "r"(addr));
}
__device__ __forceinline__ void mma_bf16(float* d, const uint32_t* a, const uint32_t* b) {
    asm volatile(
        "mma.sync.aligned.m16n8k16.row.col.f32.bf16.bf16.f32 "
        "{%0,%1,%2,%3}, {%4,%5,%6,%7}, {%8,%9}, {%0,%1,%2,%3};"
        : "+f"(d[0]), "+f"(d[1]), "+f"(d[2]), "+f"(d[3])
        : "r"(a[0]), "r"(a[1]), "r"(a[2]), "r"(a[3]), "r"(b[0]), "r"(b[1]));
}
// expm1(y) for |y| <= 0.25 via Horner; guarded exact fallback.
__device__ __forceinline__ float expm1_small(float y) {
    if (__builtin_expect(fabsf(y) > 0.25f, 0)) return expm1f(y);
    float q = 8.333333333e-3f;                 // 1/120
    q = __fmaf_rn(q, y, 4.166666667e-2f);      // 1/24
    q = __fmaf_rn(q, y, 1.666666667e-1f);      // 1/6
    q = __fmaf_rn(q, y, 0.5f);
    q = __fmaf_rn(q, y, 1.0f);
    return y * q;
}

// ---------- init ----------
__global__ void init_copy(const float* __restrict__ f) {
    int i = blockIdx.x * blockDim.x + threadIdx.x;
    ((float4*)g_frest)[i] = ((const float4*)f)[i];
    ((float4*)g_fhat)[i] = make_float4(0.f, 0.f, 0.f, 0.f);
    if (i == 0) g_sum = 0.0;
}

// ---------- prep: w_sq (raw W) + bf16 W / W^T ----------
__global__ void prep_w(const float* __restrict__ W) {
    int k = blockIdx.x;
    int tid = threadIdx.x;                           // 128 threads
    float s = 0.f;
#pragma unroll
    for (int i = 0; i < 4; i++) {
        int c = tid + i * 128;
        float v = W[k * C_ + c];
        s += v * v;
        __nv_bfloat16 b = __float2bfloat16_rn(v);
        g_wrb[k * C_ + c] = b;
        g_wtb[(size_t)c * K_ + k] = b;
    }
    for (int o = 16; o; o >>= 1) s += __shfl_xor_sync(0xffffffffu, s, o);
    __shared__ float sr[4];
    if ((tid & 31) == 0) sr[tid >> 5] = s;
    __syncthreads();
    if (tid == 0) g_wsq[k] = sr[0] + sr[1] + sr[2] + sr[3];
}

// ---------- colsum_c = sum_k tf32r(W[k,c]) (mean channel, exact fp32) ----------
__global__ void colsum_kernel(const float* __restrict__ W) {
    int c = blockIdx.x * 128 + threadIdx.x;
    float s = 0.f;
    for (int k = 0; k < K_; k++) s += tf32r(W[(size_t)k * C_ + c]);
    g_colsum[c] = s;
}

// ---------- downsample: bf16 z when splz==1, else fp32 atomic partials ----------
__global__ void downsample_kernel(int pn, int splz, float invL) {
    int c = blockIdx.y * 128 + threadIdx.x;
    int m = blockIdx.x;
    if (blockIdx.y == 0 && blockIdx.z == 0 && threadIdx.x == 0) g_S[m] = 0.f;
    int b = m / pn;
    int j = m - b * pn;
    int L = N_ / pn;
    int Lc = L / splz;
    int nb = blockIdx.z * Lc;
    const float* src = g_frest + ((size_t)b * N_ + (size_t)j * L + nb) * C_ + c;
    float s0 = 0.f, s1 = 0.f, s2 = 0.f, s3 = 0.f;
    int n = 0;
    for (; n + 4 <= Lc; n += 4) {
        s0 += src[(n + 0) * C_];
        s1 += src[(n + 1) * C_];
        s2 += src[(n + 2) * C_];
        s3 += src[(n + 3) * C_];
    }
    for (; n < Lc; n++) s0 += src[n * C_];
    float s = (s0 + s1 + s2 + s3);
    if (splz > 1) atomicAdd(&g_z[m * C_ + c], s);
    else          g_zb[m * C_ + c] = __float2bfloat16_rn(s * invL);
}

// ---------- convert fp32 z partials to bf16 (small M only) ----------
__global__ void conv_z(int total, float invL) {
    int i = blockIdx.x * 256 + threadIdx.x;
    if (i < total) g_zb[i] = __float2bfloat16_rn(g_z[i] * invL);
}

// ---------- GEMM config: 128x128 CTA tile, 128 threads (2x2 warps, 64x64 warp tile), BK=64 bf16 ----------
#define TILE_M 128
#define TILE_N 128
#define BK     64
#define A_STG_B 16384                      // 128 rows x 64 bf16 x 2B
#define STG_B   32768                      // A + B
#define GEMM_SMEM (2 * STG_B)              // 64 KB

// ---------- GEMM1 + expm1 fusion: u[m,n] = expm1(wsq[n] - 2*sum_k zb[m,k]*Wrb[n,k]) ----------
__global__ __launch_bounds__(128, 2)
void gemm_exp(const __nv_bfloat16* __restrict__ A, const __nv_bfloat16* __restrict__ B,
              __nv_bfloat16* __restrict__ E, int M)
{
    extern __shared__ char smem[];
    int tid = threadIdx.x, wid = tid >> 5, lane = tid & 31;
    int m0 = blockIdx.y * TILE_M, n0 = blockIdx.x * TILE_N;
    int wm = wid & 1, wn = wid >> 1;
    uint32_t sbase = smem_u32(smem);

    float acc[4][8][4];
#pragma unroll
    for (int i = 0; i < 4; i++)
#pragma unroll
        for (int j = 0; j < 8; j++)
#pragma unroll
            for (int q = 0; q < 4; q++) acc[i][j][q] = 0.f;

    int ld_r8 = tid >> 3;          // 0..15
    int ld_u  = tid & 7;
    int arow = wm * 64 + (lane & 15);
    int ahk  = (lane >> 4) & 1;
    int brow_b = wn * 64 + (lane & 7) + ((lane & 16) ? 8 : 0);
    int bhk  = (lane >> 3) & 1;
    const int NS = C_ / BK;        // 8

    int arow_g[8];
#pragma unroll
    for (int i = 0; i < 8; i++) arow_g[i] = min(m0 + i * 16 + ld_r8, M - 1);

    auto stage_load = [&](int kt, int buf) {
        uint32_t base = sbase + (uint32_t)buf * STG_B;
#pragma unroll
        for (int i = 0; i < 8; i++) {
            int r = i * 16 + ld_r8;
            uint32_t sa = base + ((r * 8 + (ld_u ^ (r & 7))) << 4);
            cp_async16(sa, A + (size_t)arow_g[i] * C_ + kt + ld_u * 8);
        }
#pragma unroll
        for (int i = 0; i < 8; i++) {
            int r = i * 16 + ld_r8;
            uint32_t sb2 = base + A_STG_B + ((r * 8 + (ld_u ^ (r & 7))) << 4);
            cp_async16(sb2, B + (size_t)(n0 + r) * C_ + kt + ld_u * 8);
        }
        cp_commit();
    };

    stage_load(0, 0);
    stage_load(BK, 1);

    for (int s = 0; s < NS; s++) {
        int cur = s & 1;
        if (s + 2 < NS) {
            asm volatile("cp.async.wait_group 1;" ::: "memory");
        } else {
            asm volatile("cp.async.wait_group 0;" ::: "memory");
        }
        __syncthreads();
        uint32_t sA = sbase + (uint32_t)cur * STG_B;
        uint32_t sB = sA + A_STG_B;
#pragma unroll
        for (int ks = 0; ks < 4; ks++) {
            uint32_t bfr[8][2];
#pragma unroll
            for (int g = 0; g < 4; g++) {
                uint32_t r4[4];
                int row = brow_b + g * 16;
                int unit = ks * 2 + bhk;
                uint32_t addr = sB + ((row * 8 + (unit ^ (row & 7))) << 4);
                ldm_x4(r4, addr);
                bfr[2 * g + 0][0] = r4[0]; bfr[2 * g + 0][1] = r4[1];
                bfr[2 * g + 1][0] = r4[2]; bfr[2 * g + 1][1] = r4[3];
            }
#pragma unroll
            for (int mf = 0; mf < 4; mf++) {
                uint32_t afr[4];
                int row = arow + mf * 16;
                int unit = ks * 2 + ahk;
                uint32_t addr = sA + ((row * 8 + (unit ^ (row & 7))) << 4);
                ldm_x4(afr, addr);
#pragma unroll
                for (int nf = 0; nf < 8; nf++)
                    mma_bf16(acc[mf][nf], afr, bfr[nf]);
            }
        }
        __syncthreads();
        if (s + 2 < NS) stage_load((s + 2) * BK, cur);
    }

    // ---- epilogue: u = expm1(wsq - 2*acc); store bf16; rowsum -> atomic g_S ----
    int er = lane >> 2;
    int ec = (lane & 3) * 2;
#pragma unroll
    for (int mf = 0; mf < 4; mf++) {
#pragma unroll
        for (int half = 0; half < 2; half++) {
            int row = m0 + wm * 64 + mf * 16 + er + half * 8;
            float rs = 0.f;
            if (row < M) {
                __nv_bfloat16* Erow = E + (size_t)row * K_ + n0 + wn * 64 + ec;
#pragma unroll
                for (int nf = 0; nf < 8; nf++) {
                    int ncol = n0 + wn * 64 + ec + nf * 8;
                    float u0 = expm1_small(__fadd_rn(__fmul_rn(acc[mf][nf][half * 2 + 0], -2.0f),
                                                     g_wsq[ncol]));
                    float u1 = expm1_small(__fadd_rn(__fmul_rn(acc[mf][nf][half * 2 + 1], -2.0f),
                                                     g_wsq[ncol + 1]));
                    __nv_bfloat162 v;
                    v.x = __float2bfloat16_rn(u0);
                    v.y = __float2bfloat16_rn(u1);
                    *(__nv_bfloat162*)(Erow + nf * 8) = v;
                    rs += u0 + u1;
                }
            }
            rs += __shfl_xor_sync(0xffffffffu, rs, 1);
            rs += __shfl_xor_sync(0xffffffffu, rs, 2);
            if ((lane & 3) == 0 && row < M) atomicAdd(&g_S[row], rs);
        }
    }
}

// ---------- GEMM2: h[m,c] = (colsum[c] + sum_k u[m,k]*Wtb[c,k]) / (K + Su[m]); split-K ----------
__global__ __launch_bounds__(128, 2)
void gemm_p(const __nv_bfloat16* __restrict__ U, const __nv_bfloat16* __restrict__ B,
            float* __restrict__ D, int M, int kchunk, int ksplit)
{
    extern __shared__ char smem[];
    int tid = threadIdx.x, wid = tid >> 5, lane = tid & 31;
    int m0 = blockIdx.y * TILE_M, n0 = blockIdx.x * TILE_N;
    int k0 = blockIdx.z * kchunk;
    int wm = wid & 1, wn = wid >> 1;
    uint32_t sbase = smem_u32(smem);

    float acc[4][8][4];
#pragma unroll
    for (int i = 0; i < 4; i++)
#pragma unroll
        for (int j = 0; j < 8; j++)
#pragma unroll
            for (int q = 0; q < 4; q++) acc[i][j][q] = 0.f;

    int ld_r8 = tid >> 3;
    int ld_u  = tid & 7;
    int arow = wm * 64 + (lane & 15);
    int ahk  = (lane >> 4) & 1;
    int brow_b = wn * 64 + (lane & 7) + ((lane & 16) ? 8 : 0);
    int bhk  = (lane >> 3) & 1;
    int NS = kchunk / BK;

    int arow_g[8];
#pragma unroll
    for (int i = 0; i < 8; i++) arow_g[i] = min(m0 + i * 16 + ld_r8, M - 1);

    auto stage_load = [&](int kt, int buf) {
        uint32_t base = sbase + (uint32_t)buf * STG_B;
#pragma unroll
        for (int i = 0; i < 8; i++) {
            int r = i * 16 + ld_r8;
            uint32_t sa = base + ((r * 8 + (ld_u ^ (r & 7))) << 4);
            cp_async16(sa, U + (size_t)arow_g[i] * K_ + k0 + kt + ld_u * 8);
        }
#pragma unroll
        for (int i = 0; i < 8; i++) {
            int r = i * 16 + ld_r8;
            uint32_t sb2 = base + A_STG_B + ((r * 8 + (ld_u ^ (r & 7))) << 4);
            cp_async16(sb2, B + (size_t)(n0 + r) * K_ + k0 + kt + ld_u * 8);
        }
        cp_commit();
    };

    stage_load(0, 0);
    if (NS > 1) stage_load(BK, 1);

    for (int s = 0; s < NS; s++) {
        int cur = s & 1;
        if (s + 2 < NS) {
            asm volatile("cp.async.wait_group 1;" ::: "memory");
        } else {
            asm volatile("cp.async.wait_group 0;" ::: "memory");
        }
        __syncthreads();
        uint32_t sA = sbase + (uint32_t)cur * STG_B;
        uint32_t sB = sA + A_STG_B;
#pragma unroll
        for (int ks = 0; ks < 4; ks++) {
            uint32_t bfr[8][2];
#pragma unroll
            for (int g = 0; g < 4; g++) {
                uint32_t r4[4];
                int row = brow_b + g * 16;
                int unit = ks * 2 + bhk;
                uint32_t addr = sB + ((row * 8 + (unit ^ (row & 7))) << 4);
                ldm_x4(r4, addr);
                bfr[2 * g + 0][0] = r4[0]; bfr[2 * g + 0][1] = r4[1];
                bfr[2 * g + 1][0] = r4[2]; bfr[2 * g + 1][1] = r4[3];
            }
#pragma unroll
            for (int mf = 0; mf < 4; mf++) {
                uint32_t afr[4];
                int row = arow + mf * 16;
                int unit = ks * 2 + ahk;
                uint32_t addr = sA + ((row * 8 + (unit ^ (row & 7))) << 4);
                ldm_x4(afr, addr);
#pragma unroll
                for (int nf = 0; nf < 8; nf++)
                    mma_bf16(acc[mf][nf], afr, bfr[nf]);
            }
        }
        __syncthreads();
        if (s + 2 < NS) stage_load((s + 2) * BK, cur);
    }

    // ---- epilogue: (colsum + acc) * rinv; store or atomic ----
    int er = lane >> 2;
    int ec = (lane & 3) * 2;
    int addcs = (blockIdx.z == 0) ? 1 : 0;
#pragma unroll
    for (int mf = 0; mf < 4; mf++) {
#pragma unroll
        for (int half = 0; half < 2; half++) {
            int row = m0 + wm * 64 + mf * 16 + er + half * 8;
            if (row < M) {
                float rinv = __frcp_rn(__fadd_rn((float)K_, g_S[row]));
                float* Drow = D + (size_t)row * C_ + n0 + wn * 64 + ec;
#pragma unroll
                for (int nf = 0; nf < 8; nf++) {
                    int c = n0 + wn * 64 + ec + nf * 8;
                    float a0 = acc[mf][nf][half * 2 + 0];
                    float a1 = acc[mf][nf][half * 2 + 1];
                    if (addcs) { a0 += g_colsum[c]; a1 += g_colsum[c + 1]; }
                    a0 *= rinv; a1 *= rinv;
                    if (ksplit > 1) {
                        atomicAdd(Drow + nf * 8 + 0, a0);
                        atomicAdd(Drow + nf * 8 + 1, a1);
                    } else {
                        float2 v; v.x = a0; v.y = a1;
                        *(float2*)(Drow + nf * 8) = v;
                    }
                }
            }
        }
    }
}

// ---------- upsample + f_hat/f_rest update + loss accum (+ final out) ----------
__global__ void update_kernel(const float* __restrict__ f, float* __restrict__ out,
                              int pn, int last)
{
    int i4 = blockIdx.x * blockDim.x + threadIdx.x;
    int idx = i4 << 2;
    int c = idx & (C_ - 1);
    int n = (idx >> 9) & (N_ - 1);
    int b = idx >> 19;

    float scale = (float)pn / (float)N_;
    float coord = __fsub_rn(__fmul_rn((float)n + 0.5f, scale), 0.5f);
    coord = fminf(fmaxf(coord, 0.0f), (float)(pn - 1));
    int i0 = (int)floorf(coord);
    int i1 = min(i0 + 1, pn - 1);
    float w = __fsub_rn(coord, (float)i0);
    float om = __fsub_rn(1.0f, w);

    const float* h0 = g_h + (size_t)(b * pn + i0) * C_ + c;
    const float* h1 = g_h + (size_t)(b * pn + i1) * C_ + c;
    float4 ha = *(const float4*)h0;
    float4 hb = *(const float4*)h1;
    float4 fh = *(const float4*)(g_fhat + idx);
    float4 fr = *(const float4*)(g_frest + idx);
    float4 fv = *(const float4*)(f + idx);

    float up0 = __fadd_rn(__fmul_rn(ha.x, om), __fmul_rn(hb.x, w));
    float up1 = __fadd_rn(__fmul_rn(ha.y, om), __fmul_rn(hb.y, w));
    float up2 = __fadd_rn(__fmul_rn(ha.z, om), __fmul_rn(hb.z, w));
    float up3 = __fadd_rn(__fmul_rn(ha.w, om), __fmul_rn(hb.w, w));

    fh.x = __fadd_rn(fh.x, up0); fh.y = __fadd_rn(fh.y, up1);
    fh.z = __fadd_rn(fh.z, up2); fh.w = __fadd_rn(fh.w, up3);
    fr.x = __fsub_rn(fr.x, up0); fr.y = __fsub_rn(fr.y, up1);
    fr.z = __fsub_rn(fr.z, up2); fr.w = __fsub_rn(fr.w, up3);
    *(float4*)(g_fhat + idx) = fh;
    *(float4*)(g_frest + idx) = fr;

    float t0 = __fsub_rn(fh.x, fv.x);
    float t1 = __fsub_rn(fh.y, fv.y);
    float t2 = __fsub_rn(fh.z, fv.z);
    float t3 = __fsub_rn(fh.w, fv.w);

    float sq = t0 * t0 + t1 * t1 + t2 * t2 + t3 * t3;

    if (last) {
        float4 o = make_float4(__fadd_rn(t0, fv.x), __fadd_rn(t1, fv.y),
                               __fadd_rn(t2, fv.z), __fadd_rn(t3, fv.w));
        *(float4*)(out + idx) = o;
    }

    for (int o = 16; o; o >>= 1) sq += __shfl_xor_sync(0xffffffffu, sq, o);
    __shared__ float sred[8];
    int tid = threadIdx.x;
    if ((tid & 31) == 0) sred[tid >> 5] = sq;
    __syncthreads();
    if (tid == 0) {
        float t = sred[0] + sred[1] + sred[2] + sred[3] +
                  sred[4] + sred[5] + sred[6] + sred[7];
        atomicAdd(&g_sum, (double)t);
    }
}

// ---------- scalars ----------
__global__ void finalize_kernel(float* __restrict__ out) {
    double mean = g_sum / ((double)TOT * (double)NSCALES);
    out[TOT]     = (float)(0.25 * mean);   // commit
    out[TOT + 1] = (float)mean;            // qlat
}

extern "C" void kernel_launch(void* const* d_in, const int* in_sizes, int n_in,
                              void* d_out, int out_size)
{
    const float* f = (const float*)d_in[0];   // (B, N, C) fp32
    const float* W = (const float*)d_in[1];   // (K, C)    fp32
    float* out = (float*)d_out;

    float *zp = nullptr, *hp = nullptr;
    __nv_bfloat16 *zb = nullptr, *up = nullptr, *wrb = nullptr, *wtb = nullptr;
    cudaGetSymbolAddress((void**)&zp, g_z);
    cudaGetSymbolAddress((void**)&zb, g_zb);
    cudaGetSymbolAddress((void**)&up, g_u);
    cudaGetSymbolAddress((void**)&hp, g_h);
    cudaGetSymbolAddress((void**)&wrb, g_wrb);
    cudaGetSymbolAddress((void**)&wtb, g_wtb);

    cudaFuncSetAttribute(gemm_exp, cudaFuncAttributeMaxDynamicSharedMemorySize, GEMM_SMEM);
    cudaFuncSetAttribute(gemm_p,   cudaFuncAttributeMaxDynamicSharedMemorySize, GEMM_SMEM);

    init_copy<<<TOT / 4 / 256, 256>>>(f);
    prep_w<<<K_, 128>>>(W);
    colsum_kernel<<<C_ / 128, 128>>>(W);

    for (int s = 0; s < NSCALES; s++) {
        int pn = 1 << s;
        int M = B_ * pn;
        int L = N_ / pn;
        float invL = 1.0f / (float)L;
        int mt = (M + TILE_M - 1) / TILE_M;

        // ---- downsample (split reduction when M small) ----
        int splz = 512 / M;
        if (splz < 1) splz = 1;
        if (splz > L) splz = L;
        if (splz > 1)
            cudaMemsetAsync(zp, 0, (size_t)M * C_ * sizeof(float));
        downsample_kernel<<<dim3(M, C_ / 128, splz), 128>>>(pn, splz, invL);
        if (splz > 1)
            conv_z<<<(M * C_ + 255) / 256, 256>>>(M * C_, invL);

        // ---- u = expm1(wsq - 2 zb Wrb^T), rowsums in g_S ----
        gemm_exp<<<dim3(K_ / TILE_N, mt), 128, GEMM_SMEM>>>(zb, wrb, up, M);

        // ---- h = (colsum + u @ W) / S, split-K when M small ----
        int ksplit = (M <= 2048) ? 8 : 1;
        int kchunk = K_ / ksplit;
        if (ksplit > 1)
            cudaMemsetAsync(hp, 0, (size_t)M * C_ * sizeof(float));
        gemm_p<<<dim3(C_ / TILE_N, mt, ksplit), 128, GEMM_SMEM>>>(up, wtb, hp, M, kchunk, ksplit);

        update_kernel<<<TOT / 4 / 256, 256>>>(f, out, pn, s == NSCALES - 1 ? 1 : 0);
    }
    finalize_kernel<<<1, 1>>>(out);
}

// round 12
// speedup vs baseline: 1.9285x; 1.0431x over previous
#include <cuda_runtime.h>
#include <cuda_bf16.h>
#include <math.h>
#include <stdint.h>

#define B_      32
#define N_      1024
#define C_      512
#define K_      4096
#define NSCALES 11
#define TOT     (B_*N_*C_)      // 16777216
#define MMAX    (B_*1024)       // 32768
#define ZF_TOT  (16384 * 1023)  // sum_{s=0..9} 32*2^s*512

// ---------- static device scratch ----------
__device__ float          g_fhat[TOT];
__device__ float          g_zf[ZF_TOT];            // f block-sum pyramid, scales 0..9
__device__ float          g_z[MMAX * C_];          // fhat block-sum partials
__device__ __nv_bfloat16  g_zb[MMAX * C_];         // bf16 z (GEMM1 A operand)
__device__ __nv_bfloat16  g_u[(size_t)MMAX * K_];  // u = expm1(d), bf16
__device__ float          g_h[MMAX * C_];
__device__ __nv_bfloat16  g_wrb[K_ * C_];          // bf16 W    (4096 x 512)
__device__ __nv_bfloat16  g_wtb[C_ * K_];          // bf16 W^T  (512 x 4096)
__device__ float          g_colsum[C_];            // sum_k tf32r(W[k,c])
__device__ float          g_wsq[K_];
__device__ float          g_S[MMAX];               // row sums of u
__device__ double         g_sum;

// ---------- helpers ----------
__device__ __forceinline__ float tf32r(float x) {
    float y;
    asm("cvt.rna.tf32.f32 %0, %1;" : "=f"(y) : "f"(x));
    return y;
}
__device__ __forceinline__ uint32_t smem_u32(const void* p) {
    uint32_t a;
    asm("{ .reg .u64 t; cvta.to.shared.u64 t, %1; cvt.u32.u64 %0, t; }" : "=r"(a) : "l"(p));
    return a;
}
__device__ __forceinline__ void cp_async16(uint32_t saddr, const void* gaddr) {
    asm volatile("cp.async.cg.shared.global [%0], [%1], 16;" :: "r"(saddr), "l"(gaddr));
}
__device__ __forceinline__ void cp_commit() {
    asm volatile("cp.async.commit_group;" ::: "memory");
}
__device__ __forceinline__ void ldm_x4(uint32_t* r, uint32_t addr) {
    asm volatile("ldmatrix.sync.aligned.m8n8.x4.shared.b16 {%0,%1,%2,%3}, [%4];"
                 : "=r"(r[0]), "=r"(r[1]), "=r"(r[2]), "=r"(r[3]) : "r"(addr));
}
__device__ __forceinline__ void mma_bf16(float* d, const uint32_t* a, const uint32_t* b) {
    asm volatile(
        "mma.sync.aligned.m16n8k16.row.col.f32.bf16.bf16.f32 "
        "{%0,%1,%2,%3}, {%4,%5,%6,%7}, {%8,%9}, {%0,%1,%2,%3};"
        : "+f"(d[0]), "+f"(d[1]), "+f"(d[2]), "+f"(d[3])
        : "r"(a[0]), "r"(a[1]), "r"(a[2]), "r"(a[3]), "r"(b[0]), "r"(b[1]));
}
// expm1(y) for |y| <= 0.25 via Horner; guarded exact fallback.
__device__ __forceinline__ float expm1_small(float y) {
    if (__builtin_expect(fabsf(y) > 0.25f, 0)) return expm1f(y);
    float q = 8.333333333e-3f;
    q = __fmaf_rn(q, y, 4.166666667e-2f);
    q = __fmaf_rn(q, y, 1.666666667e-1f);
    q = __fmaf_rn(q, y, 0.5f);
    q = __fmaf_rn(q, y, 1.0f);
    return y * q;
}

// ---------- init: zero fhat ----------
__global__ void init_zero() {
    int i = blockIdx.x * blockDim.x + threadIdx.x;
    ((float4*)g_fhat)[i] = make_float4(0.f, 0.f, 0.f, 0.f);
    if (i == 0) g_sum = 0.0;
}

// ---------- pyramid: dst[m,c] = src[2m,c] + src[2m+1,c] (float4) ----------
__global__ void pyr_kernel(const float* __restrict__ src, float* __restrict__ dst, int total4) {
    int j = blockIdx.x * 256 + threadIdx.x;
    if (j >= total4) return;
    int idx = j << 2;
    int c = idx & (C_ - 1);
    int so = (2 * idx - c) >> 2;
    float4 a = ((const float4*)src)[so];
    float4 b = ((const float4*)src)[so + (C_ >> 2)];
    float4 d = make_float4(a.x + b.x, a.y + b.y, a.z + b.z, a.w + b.w);
    ((float4*)dst)[j] = d;
}

// ---------- prep: w_sq (raw W) + bf16 W / W^T ----------
__global__ void prep_w(const float* __restrict__ W) {
    int k = blockIdx.x;
    int tid = threadIdx.x;                           // 128 threads
    float s = 0.f;
#pragma unroll
    for (int i = 0; i < 4; i++) {
        int c = tid + i * 128;
        float v = W[k * C_ + c];
        s += v * v;
        __nv_bfloat16 b = __float2bfloat16_rn(v);
        g_wrb[k * C_ + c] = b;
        g_wtb[(size_t)c * K_ + k] = b;
    }
    for (int o = 16; o; o >>= 1) s += __shfl_xor_sync(0xffffffffu, s, o);
    __shared__ float sr[4];
    if ((tid & 31) == 0) sr[tid >> 5] = s;
    __syncthreads();
    if (tid == 0) g_wsq[k] = sr[0] + sr[1] + sr[2] + sr[3];
}

// ---------- colsum_c = sum_k tf32r(W[k,c]) ----------
__global__ void colsum_kernel(const float* __restrict__ W) {
    int c = blockIdx.x * 128 + threadIdx.x;
    float s = 0.f;
    for (int k = 0; k < K_; k++) s += tf32r(W[(size_t)k * C_ + c]);
    g_colsum[c] = s;
}

// ---------- downsample over FHAT: zb = (zf - sum(fhat))*invL, or atomic partials ----------
__global__ void downsample_kernel(const float* __restrict__ zf, int pn, int splz, float invL) {
    int c = blockIdx.y * 128 + threadIdx.x;
    int m = blockIdx.x;
    int b = m / pn;
    int j = m - b * pn;
    int L = N_ / pn;
    int Lc = L / splz;
    int nb = blockIdx.z * Lc;
    const float* src = g_fhat + ((size_t)b * N_ + (size_t)j * L + nb) * C_ + c;
    float s0 = 0.f, s1 = 0.f, s2 = 0.f, s3 = 0.f;
    int n = 0;
    for (; n + 4 <= Lc; n += 4) {
        s0 += src[(n + 0) * C_];
        s1 += src[(n + 1) * C_];
        s2 += src[(n + 2) * C_];
        s3 += src[(n + 3) * C_];
    }
    for (; n < Lc; n++) s0 += src[n * C_];
    float s = (s0 + s1 + s2 + s3);
    if (splz > 1) atomicAdd(&g_z[m * C_ + c], s);
    else          g_zb[m * C_ + c] = __float2bfloat16_rn((zf[m * C_ + c] - s) * invL);
}

// ---------- zb = (zf - zfh_partials)*invL ----------
__global__ void conv_z(const float* __restrict__ zf, int total, float invL) {
    int i = blockIdx.x * 256 + threadIdx.x;
    if (i < total) g_zb[i] = __float2bfloat16_rn((zf[i] - g_z[i]) * invL);
}

// ---------- GEMM config: 128x128 CTA tile, 128 threads (2x2 warps, 64x64 warp tile), BK=64 bf16 ----------
#define TILE_M 128
#define TILE_N 128
#define BK     64
#define A_STG_B 16384
#define STG_B   32768
#define GEMM_SMEM (2 * STG_B)

// ---------- GEMM1 + expm1 fusion: u[m,n] = expm1(wsq[n] - 2*sum_k zb[m,k]*Wrb[n,k]) ----------
__global__ __launch_bounds__(128, 2)
void gemm_exp(const __nv_bfloat16* __restrict__ A, const __nv_bfloat16* __restrict__ B,
              __nv_bfloat16* __restrict__ E, int M)
{
    extern __shared__ char smem[];
    int tid = threadIdx.x, wid = tid >> 5, lane = tid & 31;
    int m0 = blockIdx.y * TILE_M, n0 = blockIdx.x * TILE_N;
    int wm = wid & 1, wn = wid >> 1;
    uint32_t sbase = smem_u32(smem);

    float acc[4][8][4];
#pragma unroll
    for (int i = 0; i < 4; i++)
#pragma unroll
        for (int j = 0; j < 8; j++)
#pragma unroll
            for (int q = 0; q < 4; q++) acc[i][j][q] = 0.f;

    int ld_r8 = tid >> 3;
    int ld_u  = tid & 7;
    int arow = wm * 64 + (lane & 15);
    int ahk  = (lane >> 4) & 1;
    int brow_b = wn * 64 + (lane & 7) + ((lane & 16) ? 8 : 0);
    int bhk  = (lane >> 3) & 1;
    const int NS = C_ / BK;

    int arow_g[8];
#pragma unroll
    for (int i = 0; i < 8; i++) arow_g[i] = min(m0 + i * 16 + ld_r8, M - 1);

    auto stage_load = [&](int kt, int buf) {
        uint32_t base = sbase + (uint32_t)buf * STG_B;
#pragma unroll
        for (int i = 0; i < 8; i++) {
            int r = i * 16 + ld_r8;
            uint32_t sa = base + ((r * 8 + (ld_u ^ (r & 7))) << 4);
            cp_async16(sa, A + (size_t)arow_g[i] * C_ + kt + ld_u * 8);
        }
#pragma unroll
        for (int i = 0; i < 8; i++) {
            int r = i * 16 + ld_r8;
            uint32_t sb2 = base + A_STG_B + ((r * 8 + (ld_u ^ (r & 7))) << 4);
            cp_async16(sb2, B + (size_t)(n0 + r) * C_ + kt + ld_u * 8);
        }
        cp_commit();
    };

    stage_load(0, 0);
    stage_load(BK, 1);

    for (int s = 0; s < NS; s++) {
        int cur = s & 1;
        if (s + 2 < NS) {
            asm volatile("cp.async.wait_group 1;" ::: "memory");
        } else {
            asm volatile("cp.async.wait_group 0;" ::: "memory");
        }
        __syncthreads();
        uint32_t sA = sbase + (uint32_t)cur * STG_B;
        uint32_t sB = sA + A_STG_B;
#pragma unroll
        for (int ks = 0; ks < 4; ks++) {
            uint32_t bfr[8][2];
#pragma unroll
            for (int g = 0; g < 4; g++) {
                uint32_t r4[4];
                int row = brow_b + g * 16;
                int unit = ks * 2 + bhk;
                uint32_t addr = sB + ((row * 8 + (unit ^ (row & 7))) << 4);
                ldm_x4(r4, addr);
                bfr[2 * g + 0][0] = r4[0]; bfr[2 * g + 0][1] = r4[1];
                bfr[2 * g + 1][0] = r4[2]; bfr[2 * g + 1][1] = r4[3];
            }
#pragma unroll
            for (int mf = 0; mf < 4; mf++) {
                uint32_t afr[4];
                int row = arow + mf * 16;
                int unit = ks * 2 + ahk;
                uint32_t addr = sA + ((row * 8 + (unit ^ (row & 7))) << 4);
                ldm_x4(afr, addr);
#pragma unroll
                for (int nf = 0; nf < 8; nf++)
                    mma_bf16(acc[mf][nf], afr, bfr[nf]);
            }
        }
        __syncthreads();
        if (s + 2 < NS) stage_load((s + 2) * BK, cur);
    }

    // ---- epilogue: u = expm1(wsq - 2*acc); store bf16; rowsum -> atomic g_S ----
    int er = lane >> 2;
    int ec = (lane & 3) * 2;
#pragma unroll
    for (int mf = 0; mf < 4; mf++) {
#pragma unroll
        for (int half = 0; half < 2; half++) {
            int row = m0 + wm * 64 + mf * 16 + er + half * 8;
            float rs = 0.f;
            if (row < M) {
                __nv_bfloat16* Erow = E + (size_t)row * K_ + n0 + wn * 64 + ec;
#pragma unroll
                for (int nf = 0; nf < 8; nf++) {
                    int ncol = n0 + wn * 64 + ec + nf * 8;
                    float u0 = expm1_small(__fadd_rn(__fmul_rn(acc[mf][nf][half * 2 + 0], -2.0f),
                                                     g_wsq[ncol]));
                    float u1 = expm1_small(__fadd_rn(__fmul_rn(acc[mf][nf][half * 2 + 1], -2.0f),
                                                     g_wsq[ncol + 1]));
                    __nv_bfloat162 v;
                    v.x = __float2bfloat16_rn(u0);
                    v.y = __float2bfloat16_rn(u1);
                    *(__nv_bfloat162*)(Erow + nf * 8) = v;
                    rs += u0 + u1;
                }
            }
            rs += __shfl_xor_sync(0xffffffffu, rs, 1);
            rs += __shfl_xor_sync(0xffffffffu, rs, 2);
            if ((lane & 3) == 0 && row < M) atomicAdd(&g_S[row], rs);
        }
    }
}

// ---------- GEMM2: h[m,c] = (colsum[c] + sum_k u[m,k]*Wtb[c,k]) / (K + Su[m]); split-K ----------
__global__ __launch_bounds__(128, 2)
void gemm_p(const __nv_bfloat16* __restrict__ U, const __nv_bfloat16* __restrict__ B,
            float* __restrict__ D, int M, int kchunk, int ksplit)
{
    extern __shared__ char smem[];
    int tid = threadIdx.x, wid = tid >> 5, lane = tid & 31;
    int m0 = blockIdx.y * TILE_M, n0 = blockIdx.x * TILE_N;
    int k0 = blockIdx.z * kchunk;
    int wm = wid & 1, wn = wid >> 1;
    uint32_t sbase = smem_u32(smem);

    float acc[4][8][4];
#pragma unroll
    for (int i = 0; i < 4; i++)
#pragma unroll
        for (int j = 0; j < 8; j++)
#pragma unroll
            for (int q = 0; q < 4; q++) acc[i][j][q] = 0.f;

    int ld_r8 = tid >> 3;
    int ld_u  = tid & 7;
    int arow = wm * 64 + (lane & 15);
    int ahk  = (lane >> 4) & 1;
    int brow_b = wn * 64 + (lane & 7) + ((lane & 16) ? 8 : 0);
    int bhk  = (lane >> 3) & 1;
    int NS = kchunk / BK;

    int arow_g[8];
#pragma unroll
    for (int i = 0; i < 8; i++) arow_g[i] = min(m0 + i * 16 + ld_r8, M - 1);

    auto stage_load = [&](int kt, int buf) {
        uint32_t base = sbase + (uint32_t)buf * STG_B;
#pragma unroll
        for (int i = 0; i < 8; i++) {
            int r = i * 16 + ld_r8;
            uint32_t sa = base + ((r * 8 + (ld_u ^ (r & 7))) << 4);
            cp_async16(sa, U + (size_t)arow_g[i] * K_ + k0 + kt + ld_u * 8);
        }
#pragma unroll
        for (int i = 0; i < 8; i++) {
            int r = i * 16 + ld_r8;
            uint32_t sb2 = base + A_STG_B + ((r * 8 + (ld_u ^ (r & 7))) << 4);
            cp_async16(sb2, B + (size_t)(n0 + r) * K_ + k0 + kt + ld_u * 8);
        }
        cp_commit();
    };

    stage_load(0, 0);
    if (NS > 1) stage_load(BK, 1);

    for (int s = 0; s < NS; s++) {
        int cur = s & 1;
        if (s + 2 < NS) {
            asm volatile("cp.async.wait_group 1;" ::: "memory");
        } else {
            asm volatile("cp.async.wait_group 0;" ::: "memory");
        }
        __syncthreads();
        uint32_t sA = sbase + (uint32_t)cur * STG_B;
        uint32_t sB = sA + A_STG_B;
#pragma unroll
        for (int ks = 0; ks < 4; ks++) {
            uint32_t bfr[8][2];
#pragma unroll
            for (int g = 0; g < 4; g++) {
                uint32_t r4[4];
                int row = brow_b + g * 16;
                int unit = ks * 2 + bhk;
                uint32_t addr = sB + ((row * 8 + (unit ^ (row & 7))) << 4);
                ldm_x4(r4, addr);
                bfr[2 * g + 0][0] = r4[0]; bfr[2 * g + 0][1] = r4[1];
                bfr[2 * g + 1][0] = r4[2]; bfr[2 * g + 1][1] = r4[3];
            }
#pragma unroll
            for (int mf = 0; mf < 4; mf++) {
                uint32_t afr[4];
                int row = arow + mf * 16;
                int unit = ks * 2 + ahk;
                uint32_t addr = sA + ((row * 8 + (unit ^ (row & 7))) << 4);
                ldm_x4(afr, addr);
#pragma unroll
                for (int nf = 0; nf < 8; nf++)
                    mma_bf16(acc[mf][nf], afr, bfr[nf]);
            }
        }
        __syncthreads();
        if (s + 2 < NS) stage_load((s + 2) * BK, cur);
    }

    // ---- epilogue ----
    int er = lane >> 2;
    int ec = (lane & 3) * 2;
    int addcs = (blockIdx.z == 0) ? 1 : 0;
#pragma unroll
    for (int mf = 0; mf < 4; mf++) {
#pragma unroll
        for (int half = 0; half < 2; half++) {
            int row = m0 + wm * 64 + mf * 16 + er + half * 8;
            if (row < M) {
                float rinv = __frcp_rn(__fadd_rn((float)K_, g_S[row]));
                float* Drow = D + (size_t)row * C_ + n0 + wn * 64 + ec;
#pragma unroll
                for (int nf = 0; nf < 8; nf++) {
                    int c = n0 + wn * 64 + ec + nf * 8;
                    float a0 = acc[mf][nf][half * 2 + 0];
                    float a1 = acc[mf][nf][half * 2 + 1];
                    if (addcs) { a0 += g_colsum[c]; a1 += g_colsum[c + 1]; }
                    a0 *= rinv; a1 *= rinv;
                    if (ksplit > 1) {
                        atomicAdd(Drow + nf * 8 + 0, a0);
                        atomicAdd(Drow + nf * 8 + 1, a1);
                    } else {
                        float2 v; v.x = a0; v.y = a1;
                        *(float2*)(Drow + nf * 8) = v;
                    }
                }
            }
        }
    }
}

// ---------- upsample + f_hat update + loss accum (+ final out); no f_rest ----------
__global__ void update_kernel(const float* __restrict__ f, float* __restrict__ out,
                              int pn, int last)
{
    int i4 = blockIdx.x * blockDim.x + threadIdx.x;
    int idx = i4 << 2;
    int c = idx & (C_ - 1);
    int n = (idx >> 9) & (N_ - 1);
    int b = idx >> 19;

    float scale = (float)pn / (float)N_;
    float coord = __fsub_rn(__fmul_rn((float)n + 0.5f, scale), 0.5f);
    coord = fminf(fmaxf(coord, 0.0f), (float)(pn - 1));
    int i0 = (int)floorf(coord);
    int i1 = min(i0 + 1, pn - 1);
    float w = __fsub_rn(coord, (float)i0);
    float om = __fsub_rn(1.0f, w);

    const float* h0 = g_h + (size_t)(b * pn + i0) * C_ + c;
    const float* h1 = g_h + (size_t)(b * pn + i1) * C_ + c;
    float4 ha = *(const float4*)h0;
    float4 hb = *(const float4*)h1;
    float4 fh = *(const float4*)(g_fhat + idx);
    float4 fv = *(const float4*)(f + idx);

    float up0 = __fadd_rn(__fmul_rn(ha.x, om), __fmul_rn(hb.x, w));
    float up1 = __fadd_rn(__fmul_rn(ha.y, om), __fmul_rn(hb.y, w));
    float up2 = __fadd_rn(__fmul_rn(ha.z, om), __fmul_rn(hb.z, w));
    float up3 = __fadd_rn(__fmul_rn(ha.w, om), __fmul_rn(hb.w, w));

    fh.x = __fadd_rn(fh.x, up0); fh.y = __fadd_rn(fh.y, up1);
    fh.z = __fadd_rn(fh.z, up2); fh.w = __fadd_rn(fh.w, up3);
    *(float4*)(g_fhat + idx) = fh;

    float t0 = __fsub_rn(fh.x, fv.x);
    float t1 = __fsub_rn(fh.y, fv.y);
    float t2 = __fsub_rn(fh.z, fv.z);
    float t3 = __fsub_rn(fh.w, fv.w);

    float sq = t0 * t0 + t1 * t1 + t2 * t2 + t3 * t3;

    if (last) {
        float4 o = make_float4(__fadd_rn(t0, fv.x), __fadd_rn(t1, fv.y),
                               __fadd_rn(t2, fv.z), __fadd_rn(t3, fv.w));
        *(float4*)(out + idx) = o;
    }

    for (int o = 16; o; o >>= 1) sq += __shfl_xor_sync(0xffffffffu, sq, o);
    __shared__ float sred[8];
    int tid = threadIdx.x;
    if ((tid & 31) == 0) sred[tid >> 5] = sq;
    __syncthreads();
    if (tid == 0) {
        float t = sred[0] + sred[1] + sred[2] + sred[3] +
                  sred[4] + sred[5] + sred[6] + sred[7];
        atomicAdd(&g_sum, (double)t);
    }
}

// ---------- scalars ----------
__global__ void finalize_kernel(float* __restrict__ out) {
    double mean = g_sum / ((double)TOT * (double)NSCALES);
    out[TOT]     = (float)(0.25 * mean);   // commit
    out[TOT + 1] = (float)mean;            // qlat
}

extern "C" void kernel_launch(void* const* d_in, const int* in_sizes, int n_in,
                              void* d_out, int out_size)
{
    const float* f = (const float*)d_in[0];   // (B, N, C) fp32
    const float* W = (const float*)d_in[1];   // (K, C)    fp32
    float* out = (float*)d_out;

    float *zp = nullptr, *hp = nullptr, *zf = nullptr, *Sp = nullptr;
    __nv_bfloat16 *zb = nullptr, *up = nullptr, *wrb = nullptr, *wtb = nullptr;
    cudaGetSymbolAddress((void**)&zp, g_z);
    cudaGetSymbolAddress((void**)&zf, g_zf);
    cudaGetSymbolAddress((void**)&Sp, g_S);
    cudaGetSymbolAddress((void**)&zb, g_zb);
    cudaGetSymbolAddress((void**)&up, g_u);
    cudaGetSymbolAddress((void**)&hp, g_h);
    cudaGetSymbolAddress((void**)&wrb, g_wrb);
    cudaGetSymbolAddress((void**)&wtb, g_wtb);

    cudaFuncSetAttribute(gemm_exp, cudaFuncAttributeMaxDynamicSharedMemorySize, GEMM_SMEM);
    cudaFuncSetAttribute(gemm_p,   cudaFuncAttributeMaxDynamicSharedMemorySize, GEMM_SMEM);

    init_zero<<<TOT / 4 / 256, 256>>>();
    prep_w<<<K_, 128>>>(W);
    colsum_kernel<<<C_ / 128, 128>>>(W);

    // build f block-sum pyramid: zf_s at offset 16384*((1<<s)-1), s=0..9; s=10 -> f itself
    auto zf_ptr = [&](int s) -> const float* {
        return (s == 10) ? f : (zf + 16384 * ((1 << s) - 1));
    };
    for (int s = 9; s >= 0; s--) {
        int total4 = (32 * (1 << s) * C_) / 4;
        pyr_kernel<<<(total4 + 255) / 256, 256>>>(zf_ptr(s + 1), (float*)zf_ptr(s), total4);
    }

    for (int s = 0; s < NSCALES; s++) {
        int pn = 1 << s;
        int M = B_ * pn;
        int L = N_ / pn;
        float invL = 1.0f / (float)L;
        int mt = (M + TILE_M - 1) / TILE_M;
        const float* zfs = zf_ptr(s);

        cudaMemsetAsync(Sp, 0, (size_t)M * sizeof(float));

        if (s == 0) {
            // fhat == 0: z = zf * invL
            cudaMemsetAsync(zp, 0, (size_t)M * C_ * sizeof(float));
            conv_z<<<(M * C_ + 255) / 256, 256>>>(zfs, M * C_, invL);
        } else {
            int splz = 512 / M;
            if (splz < 1) splz = 1;
            if (splz > L) splz = L;
            if (splz > 1) {
                cudaMemsetAsync(zp, 0, (size_t)M * C_ * sizeof(float));
                downsample_kernel<<<dim3(M, C_ / 128, splz), 128>>>(zfs, pn, splz, invL);
                conv_z<<<(M * C_ + 255) / 256, 256>>>(zfs, M * C_, invL);
            } else {
                downsample_kernel<<<dim3(M, C_ / 128, 1), 128>>>(zfs, pn, 1, invL);
            }
        }

        // ---- u = expm1(wsq - 2 zb Wrb^T), rowsums in g_S ----
        gemm_exp<<<dim3(K_ / TILE_N, mt), 128, GEMM_SMEM>>>(zb, wrb, up, M);

        // ---- h = (colsum + u @ W) / S, split-K when M small ----
        int ksplit = (M <= 2048) ? 8 : 1;
        int kchunk = K_ / ksplit;
        if (ksplit > 1)
            cudaMemsetAsync(hp, 0, (size_t)M * C_ * sizeof(float));
        gemm_p<<<dim3(C_ / TILE_N, mt, ksplit), 128, GEMM_SMEM>>>(up, wtb, hp, M, kchunk, ksplit);

        update_kernel<<<TOT / 4 / 256, 256>>>(f, out, pn, s == NSCALES - 1 ? 1 : 0);
    }
    finalize_kernel<<<1, 1>>>(out);
}

// round 13
// speedup vs baseline: 1.9302x; 1.0009x over previous
#include <cuda_runtime.h>
#include <cuda_bf16.h>
#include <math.h>
#include <stdint.h>

#define B_      32
#define N_      1024
#define C_      512
#define K_      4096
#define NSCALES 11
#define TOT     (B_*N_*C_)      // 16777216
#define MMAX    (B_*1024)       // 32768
#define ZF_TOT  (16384 * 1023)  // sum_{s=0..9} 32*2^s*512

// ---------- static device scratch ----------
__device__ float          g_fhat[TOT];
__device__ float          g_zf[ZF_TOT];            // f block-sum pyramid, scales 0..9
__device__ float          g_z[MMAX * C_];          // fhat block-sum partials
__device__ __nv_bfloat16  g_zb[MMAX * C_];         // bf16 z (GEMM1 A operand)
__device__ __nv_bfloat16  g_u[(size_t)MMAX * K_];  // u = expm1(d), bf16
__device__ float          g_h[MMAX * C_];
__device__ __nv_bfloat16  g_wrb[K_ * C_];          // bf16 W    (4096 x 512)
__device__ __nv_bfloat16  g_wtb[C_ * K_];          // bf16 W^T  (512 x 4096)
__device__ float          g_colsum[C_];            // sum_k tf32r(W[k,c])
__device__ float          g_wsq[K_];
__device__ float          g_S[MMAX];               // row sums of u
__device__ double         g_sum;

// ---------- helpers ----------
__device__ __forceinline__ float tf32r(float x) {
    float y;
    asm("cvt.rna.tf32.f32 %0, %1;" : "=f"(y) : "f"(x));
    return y;
}
__device__ __forceinline__ uint32_t smem_u32(const void* p) {
    uint32_t a;
    asm("{ .reg .u64 t; cvta.to.shared.u64 t, %1; cvt.u32.u64 %0, t; }" : "=r"(a) : "l"(p));
    return a;
}
__device__ __forceinline__ void cp_async16(uint32_t saddr, const void* gaddr) {
    asm volatile("cp.async.cg.shared.global [%0], [%1], 16;" :: "r"(saddr), "l"(gaddr));
}
__device__ __forceinline__ void cp_commit() {
    asm volatile("cp.async.commit_group;" ::: "memory");
}
__device__ __forceinline__ void ldm_x4(uint32_t* r, uint32_t addr) {
    asm volatile("ldmatrix.sync.aligned.m8n8.x4.shared.b16 {%0,%1,%2,%3}, [%4];"
                 : "=r"(r[0]), "=r"(r[1]), "=r"(r[2]), "=r"(r[3]) : "r"(addr));
}
__device__ __forceinline__ void mma_bf16(float* d, const uint32_t* a, const uint32_t* b) {
    asm volatile(
        "mma.sync.aligned.m16n8k16.row.col.f32.bf16.bf16.f32 "
        "{%0,%1,%2,%3}, {%4,%5,%6,%7}, {%8,%9}, {%0,%1,%2,%3};"
        : "+f"(d[0]), "+f"(d[1]), "+f"(d[2]), "+f"(d[3])
        : "r"(a[0]), "r"(a[1]), "r"(a[2]), "r"(a[3]), "r"(b[0]), "r"(b[1]));
}
// expm1(y) for |y| <= 0.25 via Horner; guarded exact fallback.
__device__ __forceinline__ float expm1_small(float y) {
    if (__builtin_expect(fabsf(y) > 0.25f, 0)) return expm1f(y);
    float q = 8.333333333e-3f;
    q = __fmaf_rn(q, y, 4.166666667e-2f);
    q = __fmaf_rn(q, y, 1.666666667e-1f);
    q = __fmaf_rn(q, y, 0.5f);
    q = __fmaf_rn(q, y, 1.0f);
    return y * q;
}

// ---------- init: zero fhat ----------
__global__ void init_zero() {
    int i = blockIdx.x * blockDim.x + threadIdx.x;
    ((float4*)g_fhat)[i] = make_float4(0.f, 0.f, 0.f, 0.f);
    if (i == 0) g_sum = 0.0;
}

// ---------- pyramid: dst[m,c] = src[2m,c] + src[2m+1,c] (float4) ----------
__global__ void pyr_kernel(const float* __restrict__ src, float* __restrict__ dst, int total4) {
    int j = blockIdx.x * 256 + threadIdx.x;
    if (j >= total4) return;
    int idx = j << 2;
    int c = idx & (C_ - 1);
    int so = (2 * idx - c) >> 2;
    float4 a = ((const float4*)src)[so];
    float4 b = ((const float4*)src)[so + (C_ >> 2)];
    float4 d = make_float4(a.x + b.x, a.y + b.y, a.z + b.z, a.w + b.w);
    ((float4*)dst)[j] = d;
}

// ---------- prep: w_sq (raw W) + bf16 W / W^T ----------
__global__ void prep_w(const float* __restrict__ W) {
    int k = blockIdx.x;
    int tid = threadIdx.x;                           // 128 threads
    float s = 0.f;
#pragma unroll
    for (int i = 0; i < 4; i++) {
        int c = tid + i * 128;
        float v = W[k * C_ + c];
        s += v * v;
        __nv_bfloat16 b = __float2bfloat16_rn(v);
        g_wrb[k * C_ + c] = b;
        g_wtb[(size_t)c * K_ + k] = b;
    }
    for (int o = 16; o; o >>= 1) s += __shfl_xor_sync(0xffffffffu, s, o);
    __shared__ float sr[4];
    if ((tid & 31) == 0) sr[tid >> 5] = s;
    __syncthreads();
    if (tid == 0) g_wsq[k] = sr[0] + sr[1] + sr[2] + sr[3];
}

// ---------- colsum_c = sum_k tf32r(W[k,c]) ----------
__global__ void colsum_kernel(const float* __restrict__ W) {
    int c = blockIdx.x * 128 + threadIdx.x;
    float s = 0.f;
    for (int k = 0; k < K_; k++) s += tf32r(W[(size_t)k * C_ + c]);
    g_colsum[c] = s;
}

// ---------- downsample over FHAT: zb = (zf - sum(fhat))*invL, or atomic partials ----------
__global__ void downsample_kernel(const float* __restrict__ zf, int pn, int splz, float invL) {
    int c = blockIdx.y * 128 + threadIdx.x;
    int m = blockIdx.x;
    int b = m / pn;
    int j = m - b * pn;
    int L = N_ / pn;
    int Lc = L / splz;
    int nb = blockIdx.z * Lc;
    const float* src = g_fhat + ((size_t)b * N_ + (size_t)j * L + nb) * C_ + c;
    float s0 = 0.f, s1 = 0.f, s2 = 0.f, s3 = 0.f;
    int n = 0;
    for (; n + 4 <= Lc; n += 4) {
        s0 += src[(n + 0) * C_];
        s1 += src[(n + 1) * C_];
        s2 += src[(n + 2) * C_];
        s3 += src[(n + 3) * C_];
    }
    for (; n < Lc; n++) s0 += src[n * C_];
    float s = (s0 + s1 + s2 + s3);
    if (splz > 1) atomicAdd(&g_z[m * C_ + c], s);
    else          g_zb[m * C_ + c] = __float2bfloat16_rn((zf[m * C_ + c] - s) * invL);
}

// ---------- zb = (zf - zfh_partials)*invL ----------
__global__ void conv_z(const float* __restrict__ zf, int total, float invL) {
    int i = blockIdx.x * 256 + threadIdx.x;
    if (i < total) g_zb[i] = __float2bfloat16_rn((zf[i] - g_z[i]) * invL);
}

// ---------- GEMM config: 128x128 CTA tile, 128 threads (2x2 warps, 64x64 warp tile), BK=64 bf16,
//            3-stage cp.async pipeline, single barrier per K-iteration ----------
#define TILE_M 128
#define TILE_N 128
#define BK     64
#define A_STG_B 16384
#define STG_B   32768
#define GEMM_SMEM (3 * STG_B)              // 96 KB

// ---------- GEMM1 + expm1 fusion ----------
__global__ __launch_bounds__(128, 2)
void gemm_exp(const __nv_bfloat16* __restrict__ A, const __nv_bfloat16* __restrict__ B,
              __nv_bfloat16* __restrict__ E, int M)
{
    extern __shared__ char smem[];
    int tid = threadIdx.x, wid = tid >> 5, lane = tid & 31;
    int m0 = blockIdx.y * TILE_M, n0 = blockIdx.x * TILE_N;
    int wm = wid & 1, wn = wid >> 1;
    uint32_t sbase = smem_u32(smem);

    float acc[4][8][4];
#pragma unroll
    for (int i = 0; i < 4; i++)
#pragma unroll
        for (int j = 0; j < 8; j++)
#pragma unroll
            for (int q = 0; q < 4; q++) acc[i][j][q] = 0.f;

    int ld_r8 = tid >> 3;
    int ld_u  = tid & 7;
    int arow = wm * 64 + (lane & 15);
    int ahk  = (lane >> 4) & 1;
    int brow_b = wn * 64 + (lane & 7) + ((lane & 16) ? 8 : 0);
    int bhk  = (lane >> 3) & 1;
    const int NS = C_ / BK;

    int arow_g[8];
#pragma unroll
    for (int i = 0; i < 8; i++) arow_g[i] = min(m0 + i * 16 + ld_r8, M - 1);

    auto stage_load = [&](int kt, int buf) {
        uint32_t base = sbase + (uint32_t)buf * STG_B;
#pragma unroll
        for (int i = 0; i < 8; i++) {
            int r = i * 16 + ld_r8;
            uint32_t sa = base + ((r * 8 + (ld_u ^ (r & 7))) << 4);
            cp_async16(sa, A + (size_t)arow_g[i] * C_ + kt + ld_u * 8);
        }
#pragma unroll
        for (int i = 0; i < 8; i++) {
            int r = i * 16 + ld_r8;
            uint32_t sb2 = base + A_STG_B + ((r * 8 + (ld_u ^ (r & 7))) << 4);
            cp_async16(sb2, B + (size_t)(n0 + r) * C_ + kt + ld_u * 8);
        }
        cp_commit();
    };

    stage_load(0, 0);
    stage_load(BK, 1);

    int buf = 0;
    for (int s = 0; s < NS; s++) {
        if (s + 1 < NS) asm volatile("cp.async.wait_group 1;" ::: "memory");
        else            asm volatile("cp.async.wait_group 0;" ::: "memory");
        __syncthreads();
        if (s + 2 < NS) {
            int nb = buf + 2; if (nb >= 3) nb -= 3;
            stage_load((s + 2) * BK, nb);
        }
        uint32_t sA = sbase + (uint32_t)buf * STG_B;
        uint32_t sB = sA + A_STG_B;
#pragma unroll
        for (int ks = 0; ks < 4; ks++) {
            uint32_t bfr[8][2];
#pragma unroll
            for (int g = 0; g < 4; g++) {
                uint32_t r4[4];
                int row = brow_b + g * 16;
                int unit = ks * 2 + bhk;
                uint32_t addr = sB + ((row * 8 + (unit ^ (row & 7))) << 4);
                ldm_x4(r4, addr);
                bfr[2 * g + 0][0] = r4[0]; bfr[2 * g + 0][1] = r4[1];
                bfr[2 * g + 1][0] = r4[2]; bfr[2 * g + 1][1] = r4[3];
            }
#pragma unroll
            for (int mf = 0; mf < 4; mf++) {
                uint32_t afr[4];
                int row = arow + mf * 16;
                int unit = ks * 2 + ahk;
                uint32_t addr = sA + ((row * 8 + (unit ^ (row & 7))) << 4);
                ldm_x4(afr, addr);
#pragma unroll
                for (int nf = 0; nf < 8; nf++)
                    mma_bf16(acc[mf][nf], afr, bfr[nf]);
            }
        }
        buf++; if (buf >= 3) buf -= 3;
    }

    // ---- epilogue: u = expm1(wsq - 2*acc); store bf16; rowsum -> atomic g_S ----
    int er = lane >> 2;
    int ec = (lane & 3) * 2;
#pragma unroll
    for (int mf = 0; mf < 4; mf++) {
#pragma unroll
        for (int half = 0; half < 2; half++) {
            int row = m0 + wm * 64 + mf * 16 + er + half * 8;
            float rs = 0.f;
            if (row < M) {
                __nv_bfloat16* Erow = E + (size_t)row * K_ + n0 + wn * 64 + ec;
#pragma unroll
                for (int nf = 0; nf < 8; nf++) {
                    int ncol = n0 + wn * 64 + ec + nf * 8;
                    float u0 = expm1_small(__fadd_rn(__fmul_rn(acc[mf][nf][half * 2 + 0], -2.0f),
                                                     g_wsq[ncol]));
                    float u1 = expm1_small(__fadd_rn(__fmul_rn(acc[mf][nf][half * 2 + 1], -2.0f),
                                                     g_wsq[ncol + 1]));
                    __nv_bfloat162 v;
                    v.x = __float2bfloat16_rn(u0);
                    v.y = __float2bfloat16_rn(u1);
                    *(__nv_bfloat162*)(Erow + nf * 8) = v;
                    rs += u0 + u1;
                }
            }
            rs += __shfl_xor_sync(0xffffffffu, rs, 1);
            rs += __shfl_xor_sync(0xffffffffu, rs, 2);
            if ((lane & 3) == 0 && row < M) atomicAdd(&g_S[row], rs);
        }
    }
}

// ---------- GEMM2: h[m,c] = (colsum[c] + sum_k u[m,k]*Wtb[c,k]) / (K + Su[m]); split-K ----------
__global__ __launch_bounds__(128, 2)
void gemm_p(const __nv_bfloat16* __restrict__ U, const __nv_bfloat16* __restrict__ B,
            float* __restrict__ D, int M, int kchunk, int ksplit)
{
    extern __shared__ char smem[];
    int tid = threadIdx.x, wid = tid >> 5, lane = tid & 31;
    int m0 = blockIdx.y * TILE_M, n0 = blockIdx.x * TILE_N;
    int k0 = blockIdx.z * kchunk;
    int wm = wid & 1, wn = wid >> 1;
    uint32_t sbase = smem_u32(smem);

    float acc[4][8][4];
#pragma unroll
    for (int i = 0; i < 4; i++)
#pragma unroll
        for (int j = 0; j < 8; j++)
#pragma unroll
            for (int q = 0; q < 4; q++) acc[i][j][q] = 0.f;

    int ld_r8 = tid >> 3;
    int ld_u  = tid & 7;
    int arow = wm * 64 + (lane & 15);
    int ahk  = (lane >> 4) & 1;
    int brow_b = wn * 64 + (lane & 7) + ((lane & 16) ? 8 : 0);
    int bhk  = (lane >> 3) & 1;
    int NS = kchunk / BK;

    int arow_g[8];
#pragma unroll
    for (int i = 0; i < 8; i++) arow_g[i] = min(m0 + i * 16 + ld_r8, M - 1);

    auto stage_load = [&](int kt, int buf) {
        uint32_t base = sbase + (uint32_t)buf * STG_B;
#pragma unroll
        for (int i = 0; i < 8; i++) {
            int r = i * 16 + ld_r8;
            uint32_t sa = base + ((r * 8 + (ld_u ^ (r & 7))) << 4);
            cp_async16(sa, U + (size_t)arow_g[i] * K_ + k0 + kt + ld_u * 8);
        }
#pragma unroll
        for (int i = 0; i < 8; i++) {
            int r = i * 16 + ld_r8;
            uint32_t sb2 = base + A_STG_B + ((r * 8 + (ld_u ^ (r & 7))) << 4);
            cp_async16(sb2, B + (size_t)(n0 + r) * K_ + k0 + kt + ld_u * 8);
        }
        cp_commit();
    };

    stage_load(0, 0);
    if (NS > 1) stage_load(BK, 1);

    int buf = 0;
    for (int s = 0; s < NS; s++) {
        if (s + 1 < NS) asm volatile("cp.async.wait_group 1;" ::: "memory");
        else            asm volatile("cp.async.wait_group 0;" ::: "memory");
        __syncthreads();
        if (s + 2 < NS) {
            int nb = buf + 2; if (nb >= 3) nb -= 3;
            stage_load((s + 2) * BK, nb);
        }
        uint32_t sA = sbase + (uint32_t)buf * STG_B;
        uint32_t sB = sA + A_STG_B;
#pragma unroll
        for (int ks = 0; ks < 4; ks++) {
            uint32_t bfr[8][2];
#pragma unroll
            for (int g = 0; g < 4; g++) {
                uint32_t r4[4];
                int row = brow_b + g * 16;
                int unit = ks * 2 + bhk;
                uint32_t addr = sB + ((row * 8 + (unit ^ (row & 7))) << 4);
                ldm_x4(r4, addr);
                bfr[2 * g + 0][0] = r4[0]; bfr[2 * g + 0][1] = r4[1];
                bfr[2 * g + 1][0] = r4[2]; bfr[2 * g + 1][1] = r4[3];
            }
#pragma unroll
            for (int mf = 0; mf < 4; mf++) {
                uint32_t afr[4];
                int row = arow + mf * 16;
                int unit = ks * 2 + ahk;
                uint32_t addr = sA + ((row * 8 + (unit ^ (row & 7))) << 4);
                ldm_x4(afr, addr);
#pragma unroll
                for (int nf = 0; nf < 8; nf++)
                    mma_bf16(acc[mf][nf], afr, bfr[nf]);
            }
        }
        buf++; if (buf >= 3) buf -= 3;
    }

    // ---- epilogue ----
    int er = lane >> 2;
    int ec = (lane & 3) * 2;
    int addcs = (blockIdx.z == 0) ? 1 : 0;
#pragma unroll
    for (int mf = 0; mf < 4; mf++) {
#pragma unroll
        for (int half = 0; half < 2; half++) {
            int row = m0 + wm * 64 + mf * 16 + er + half * 8;
            if (row < M) {
                float rinv = __frcp_rn(__fadd_rn((float)K_, g_S[row]));
                float* Drow = D + (size_t)row * C_ + n0 + wn * 64 + ec;
#pragma unroll
                for (int nf = 0; nf < 8; nf++) {
                    int c = n0 + wn * 64 + ec + nf * 8;
                    float a0 = acc[mf][nf][half * 2 + 0];
                    float a1 = acc[mf][nf][half * 2 + 1];
                    if (addcs) { a0 += g_colsum[c]; a1 += g_colsum[c + 1]; }
                    a0 *= rinv; a1 *= rinv;
                    if (ksplit > 1) {
                        atomicAdd(Drow + nf * 8 + 0, a0);
                        atomicAdd(Drow + nf * 8 + 1, a1);
                    } else {
                        float2 v; v.x = a0; v.y = a1;
                        *(float2*)(Drow + nf * 8) = v;
                    }
                }
            }
        }
    }
}

// ---------- upsample + f_hat update + loss accum (+ final out) ----------
__global__ void update_kernel(const float* __restrict__ f, float* __restrict__ out,
                              int pn, int last)
{
    int i4 = blockIdx.x * blockDim.x + threadIdx.x;
    int idx = i4 << 2;
    int c = idx & (C_ - 1);
    int n = (idx >> 9) & (N_ - 1);
    int b = idx >> 19;

    float scale = (float)pn / (float)N_;
    float coord = __fsub_rn(__fmul_rn((float)n + 0.5f, scale), 0.5f);
    coord = fminf(fmaxf(coord, 0.0f), (float)(pn - 1));
    int i0 = (int)floorf(coord);
    int i1 = min(i0 + 1, pn - 1);
    float w = __fsub_rn(coord, (float)i0);
    float om = __fsub_rn(1.0f, w);

    const float* h0 = g_h + (size_t)(b * pn + i0) * C_ + c;
    const float* h1 = g_h + (size_t)(b * pn + i1) * C_ + c;
    float4 ha = *(const float4*)h0;
    float4 hb = *(const float4*)h1;
    float4 fh = *(const float4*)(g_fhat + idx);
    float4 fv = *(const float4*)(f + idx);

    float up0 = __fadd_rn(__fmul_rn(ha.x, om), __fmul_rn(hb.x, w));
    float up1 = __fadd_rn(__fmul_rn(ha.y, om), __fmul_rn(hb.y, w));
    float up2 = __fadd_rn(__fmul_rn(ha.z, om), __fmul_rn(hb.z, w));
    float up3 = __fadd_rn(__fmul_rn(ha.w, om), __fmul_rn(hb.w, w));

    fh.x = __fadd_rn(fh.x, up0); fh.y = __fadd_rn(fh.y, up1);
    fh.z = __fadd_rn(fh.z, up2); fh.w = __fadd_rn(fh.w, up3);
    *(float4*)(g_fhat + idx) = fh;

    float t0 = __fsub_rn(fh.x, fv.x);
    float t1 = __fsub_rn(fh.y, fv.y);
    float t2 = __fsub_rn(fh.z, fv.z);
    float t3 = __fsub_rn(fh.w, fv.w);

    float sq = t0 * t0 + t1 * t1 + t2 * t2 + t3 * t3;

    if (last) {
        float4 o = make_float4(__fadd_rn(t0, fv.x), __fadd_rn(t1, fv.y),
                               __fadd_rn(t2, fv.z), __fadd_rn(t3, fv.w));
        *(float4*)(out + idx) = o;
    }

    for (int o = 16; o; o >>= 1) sq += __shfl_xor_sync(0xffffffffu, sq, o);
    __shared__ float sred[8];
    int tid = threadIdx.x;
    if ((tid & 31) == 0) sred[tid >> 5] = sq;
    __syncthreads();
    if (tid == 0) {
        float t = sred[0] + sred[1] + sred[2] + sred[3] +
                  sred[4] + sred[5] + sred[6] + sred[7];
        atomicAdd(&g_sum, (double)t);
    }
}

// ---------- scalars ----------
__global__ void finalize_kernel(float* __restrict__ out) {
    double mean = g_sum / ((double)TOT * (double)NSCALES);
    out[TOT]     = (float)(0.25 * mean);   // commit
    out[TOT + 1] = (float)mean;            // qlat
}

extern "C" void kernel_launch(void* const* d_in, const int* in_sizes, int n_in,
                              void* d_out, int out_size)
{
    const float* f = (const float*)d_in[0];   // (B, N, C) fp32
    const float* W = (const float*)d_in[1];   // (K, C)    fp32
    float* out = (float*)d_out;

    float *zp = nullptr, *hp = nullptr, *zf = nullptr, *Sp = nullptr;
    __nv_bfloat16 *zb = nullptr, *up = nullptr, *wrb = nullptr, *wtb = nullptr;
    cudaGetSymbolAddress((void**)&zp, g_z);
    cudaGetSymbolAddress((void**)&zf, g_zf);
    cudaGetSymbolAddress((void**)&Sp, g_S);
    cudaGetSymbolAddress((void**)&zb, g_zb);
    cudaGetSymbolAddress((void**)&up, g_u);
    cudaGetSymbolAddress((void**)&hp, g_h);
    cudaGetSymbolAddress((void**)&wrb, g_wrb);
    cudaGetSymbolAddress((void**)&wtb, g_wtb);

    cudaFuncSetAttribute(gemm_exp, cudaFuncAttributeMaxDynamicSharedMemorySize, GEMM_SMEM);
    cudaFuncSetAttribute(gemm_p,   cudaFuncAttributeMaxDynamicSharedMemorySize, GEMM_SMEM);

    init_zero<<<TOT / 4 / 256, 256>>>();
    prep_w<<<K_, 128>>>(W);
    colsum_kernel<<<C_ / 128, 128>>>(W);

    // build f block-sum pyramid: zf_s at offset 16384*((1<<s)-1), s=0..9; s=10 -> f itself
    auto zf_ptr = [&](int s) -> const float* {
        return (s == 10) ? f : (zf + 16384 * ((1 << s) - 1));
    };
    for (int s = 9; s >= 0; s--) {
        int total4 = (32 * (1 << s) * C_) / 4;
        pyr_kernel<<<(total4 + 255) / 256, 256>>>(zf_ptr(s + 1), (float*)zf_ptr(s), total4);
    }

    for (int s = 0; s < NSCALES; s++) {
        int pn = 1 << s;
        int M = B_ * pn;
        int L = N_ / pn;
        float invL = 1.0f / (float)L;
        int mt = (M + TILE_M - 1) / TILE_M;
        const float* zfs = zf_ptr(s);

        cudaMemsetAsync(Sp, 0, (size_t)M * sizeof(float));

        if (s == 0) {
            cudaMemsetAsync(zp, 0, (size_t)M * C_ * sizeof(float));
            conv_z<<<(M * C_ + 255) / 256, 256>>>(zfs, M * C_, invL);
        } else {
            int splz = 512 / M;
            if (splz < 1) splz = 1;
            if (splz > L) splz = L;
            if (splz > 1) {
                cudaMemsetAsync(zp, 0, (size_t)M * C_ * sizeof(float));
                downsample_kernel<<<dim3(M, C_ / 128, splz), 128>>>(zfs, pn, splz, invL);
                conv_z<<<(M * C_ + 255) / 256, 256>>>(zfs, M * C_, invL);
            } else {
                downsample_kernel<<<dim3(M, C_ / 128, 1), 128>>>(zfs, pn, 1, invL);
            }
        }

        // ---- u = expm1(wsq - 2 zb Wrb^T), rowsums in g_S ----
        gemm_exp<<<dim3(K_ / TILE_N, mt), 128, GEMM_SMEM>>>(zb, wrb, up, M);

        // ---- h = (colsum + u @ W) / S, split-K when M small ----
        int ksplit = (M <= 2048) ? 8 : 1;
        int kchunk = K_ / ksplit;
        if (ksplit > 1)
            cudaMemsetAsync(hp, 0, (size_t)M * C_ * sizeof(float));
        gemm_p<<<dim3(C_ / TILE_N, mt, ksplit), 128, GEMM_SMEM>>>(up, wtb, hp, M, kchunk, ksplit);

        update_kernel<<<TOT / 4 / 256, 256>>>(f, out, pn, s == NSCALES - 1 ? 1 : 0);
    }
    finalize_kernel<<<1, 1>>>(out);
}